// round 13
// baseline (speedup 1.0000x reference)
#include <cuda_runtime.h>
#include <cuda_fp16.h>
#include <cstdint>

#define BB 8
#define TT 1024
#define DD 1024
#define FF 4096
#define MM (BB*TT)          // 8192 rows
#define D4 (DD/4)
#define N3 (3*DD)           // fused KVR buffer width

// ---------------- scratch (static device allocations; allowed) ----------------
__device__ float    g_xn [MM*DD];
__device__ unsigned g_mk [MM*DD/2];   // half2-packed GEMM A operands
__device__ unsigned g_mv [MM*DD/2];
__device__ unsigned g_mr [MM*DD/2];
__device__ __half   g_kvr[MM*N3];     // K|V|R outputs interleaved per row (half)
__device__ __half   g_rw [MM*DD];     // r * wkv (half, GEMM A operand)
__device__ float    g_x1 [MM*DD];
__device__ float    g_xn2[MM*DD];
__device__ unsigned g_mck[MM*DD/2];
__device__ unsigned g_mcr[MM*DD/2];
__device__ __half   g_kc [MM*FF];     // relu^2 out (half, GEMM A operand)
__device__ float    g_rc [MM*DD];
// k-pair-packed fp16 weights: word(kh,n) = {h(W[2kh][n]), h(W[2kh+1][n])}
__device__ unsigned g_pWk[(DD/2)*DD];
__device__ unsigned g_pWv[(DD/2)*DD];
__device__ unsigned g_pWr[(DD/2)*DD];
__device__ unsigned g_pWo[(DD/2)*DD];
__device__ unsigned g_pCr[(DD/2)*DD];
__device__ unsigned g_pCk[(DD/2)*FF];
__device__ unsigned g_pCv[(FF/2)*DD];

// ---------------- weight pack: fp32 [Kd][Nd] -> half2 words [Kd/2][Nd] ----------------
__global__ void __launch_bounds__(256) pack_w(
    const float* __restrict__ in, unsigned* __restrict__ out, int Kd, int Nd)
{
    const int i = blockIdx.x * blockDim.x + threadIdx.x;
    const int tot = (Kd >> 1) * Nd;
    if (i >= tot) return;
    const int kh = i / Nd, n = i - kh * Nd;
    const float lo = in[(size_t)(2 * kh)     * Nd + n];
    const float hi = in[(size_t)(2 * kh + 1) * Nd + n];
    __half2 h = __floats2half2_rn(lo, hi);
    out[i] = *(unsigned*)&h;
}

// ---------------- LayerNorm ----------------
__global__ void __launch_bounds__(256) ln_kernel(
    const float* __restrict__ x, const float* __restrict__ g,
    const float* __restrict__ b, float* __restrict__ y,
    float* __restrict__ last)
{
    const int row = blockIdx.x;
    const float4* xr = (const float4*)(x + (size_t)row * DD);
    float4 v = xr[threadIdx.x];
    float s  = v.x + v.y + v.z + v.w;
    float ss = v.x*v.x + v.y*v.y + v.z*v.z + v.w*v.w;
#pragma unroll
    for (int o = 16; o; o >>= 1) {
        s  += __shfl_xor_sync(0xffffffffu, s,  o);
        ss += __shfl_xor_sync(0xffffffffu, ss, o);
    }
    __shared__ float sh[16];
    const int w = threadIdx.x >> 5, l = threadIdx.x & 31;
    if (l == 0) { sh[w] = s; sh[8 + w] = ss; }
    __syncthreads();
    s = 0.f; ss = 0.f;
#pragma unroll
    for (int i = 0; i < 8; i++) { s += sh[i]; ss += sh[8 + i]; }
    const float mean = s * (1.0f / DD);
    const float var  = ss * (1.0f / DD) - mean * mean;
    const float rstd = rsqrtf(var + 1e-3f);

    float4 gg = ((const float4*)g)[threadIdx.x];
    float4 bb = ((const float4*)b)[threadIdx.x];
    float4 o;
    o.x = (v.x - mean) * rstd * gg.x + bb.x;
    o.y = (v.y - mean) * rstd * gg.y + bb.y;
    o.z = (v.z - mean) * rstd * gg.z + bb.z;
    o.w = (v.w - mean) * rstd * gg.w + bb.w;
    ((float4*)(y + (size_t)row * DD))[threadIdx.x] = o;
    if (last && (row % TT) == (TT - 1)) {
        ((float4*)(last + (size_t)(row / TT) * DD))[threadIdx.x] = o;
    }
}

// ---------------- token-shift + lerp mixing -> half-packed outputs ----------------
template<int NOUT>
__global__ void __launch_bounds__(256) mix_kernel(
    const float* __restrict__ xn, const float* __restrict__ x0,
    const float* __restrict__ m0, const float* __restrict__ m1, const float* __restrict__ m2,
    unsigned* __restrict__ o0, unsigned* __restrict__ o1, unsigned* __restrict__ o2)
{
    const int i4 = blockIdx.x * blockDim.x + threadIdx.x;
    if (i4 >= MM * D4) return;
    const int d4 = i4 % D4;
    const int bt = i4 / D4;
    const int t = bt % TT, b = bt / TT;
    float4 xc = ((const float4*)xn)[i4];
    float4 xp = (t == 0) ? ((const float4*)x0)[b * D4 + d4]
                         : ((const float4*)xn)[i4 - D4];
    {
        float4 m = ((const float4*)m0)[d4];
        __half2 p0 = __floats2half2_rn(xp.x + (xc.x - xp.x) * m.x, xp.y + (xc.y - xp.y) * m.y);
        __half2 p1 = __floats2half2_rn(xp.z + (xc.z - xp.z) * m.z, xp.w + (xc.w - xp.w) * m.w);
        uint2 wv; wv.x = *(unsigned*)&p0; wv.y = *(unsigned*)&p1;
        ((uint2*)o0)[i4] = wv;
    }
    if (NOUT >= 2) {
        float4 m = ((const float4*)m1)[d4];
        __half2 p0 = __floats2half2_rn(xp.x + (xc.x - xp.x) * m.x, xp.y + (xc.y - xp.y) * m.y);
        __half2 p1 = __floats2half2_rn(xp.z + (xc.z - xp.z) * m.z, xp.w + (xc.w - xp.w) * m.w);
        uint2 wv; wv.x = *(unsigned*)&p0; wv.y = *(unsigned*)&p1;
        ((uint2*)o1)[i4] = wv;
    }
    if (NOUT >= 3) {
        float4 m = ((const float4*)m2)[d4];
        __half2 p0 = __floats2half2_rn(xp.x + (xc.x - xp.x) * m.x, xp.y + (xc.y - xp.y) * m.y);
        __half2 p1 = __floats2half2_rn(xp.z + (xc.z - xp.z) * m.z, xp.w + (xc.w - xp.w) * m.w);
        uint2 wv; wv.x = *(unsigned*)&p0; wv.y = *(unsigned*)&p1;
        ((uint2*)o2)[i4] = wv;
    }
}

// ---------------- WKV scan: half KVR input (row stride 3072), 4-deep prefetch ----------------
__global__ void __launch_bounds__(64) wkv_kernel(
    const __half* __restrict__ kvr,
    const float* __restrict__ a0, const float* __restrict__ b0, const float* __restrict__ p0,
    const float* __restrict__ decay, const float* __restrict__ first,
    __half* __restrict__ rw,
    float* __restrict__ aa_o, float* __restrict__ bb_o, float* __restrict__ pp_o)
{
    const int idx = blockIdx.x * blockDim.x + threadIdx.x;
    if (idx >= BB * DD) return;
    const int d = idx % DD, b = idx / DD;
    float aa = a0[idx], bb = b0[idx], pp = p0[idx];
    const float w = -expf(decay[d]);
    const float u = first[d];
    const size_t base  = (size_t)b * TT * N3 + d;    // k: +0, v: +DD, r: +2*DD
    const size_t baseW = (size_t)b * TT * DD + d;

    float kb[4], vb[4], rb[4];
#pragma unroll
    for (int j = 0; j < 4; j++) {
        const size_t off = base + (size_t)j * N3;
        kb[j] = __half2float(kvr[off]);
        vb[j] = __half2float(kvr[off + DD]);
        rb[j] = __half2float(kvr[off + 2 * DD]);
    }

    for (int t0 = 0; t0 < TT; t0 += 4) {
        float kn[4], vn[4], rn[4];
        if (t0 + 4 < TT) {
#pragma unroll
            for (int j = 0; j < 4; j++) {
                const size_t off = base + (size_t)(t0 + 4 + j) * N3;
                kn[j] = __half2float(kvr[off]);
                vn[j] = __half2float(kvr[off + DD]);
                rn[j] = __half2float(kvr[off + 2 * DD]);
            }
        } else {
#pragma unroll
            for (int j = 0; j < 4; j++) { kn[j] = 0.f; vn[j] = 0.f; rn[j] = 0.f; }
        }
#pragma unroll
        for (int j = 0; j < 4; j++) {
            const float kt = kb[j], vt = vb[j], rt = rb[j];
            float ww = u + kt;
            float p  = fmaxf(pp, ww);
            float e1 = expf(pp - p), e2 = expf(ww - p);
            float wkv = (e1 * aa + e2 * vt) / (e1 * bb + e2);
            rw[baseW + (size_t)(t0 + j) * DD] = __float2half_rn(rt * wkv);
            float ww2 = pp + w;
            float p2  = fmaxf(ww2, kt);
            float e1b = expf(ww2 - p2), e2b = expf(kt - p2);
            aa = e1b * aa + e2b * vt;
            bb = e1b * bb + e2b;
            pp = p2;
        }
#pragma unroll
        for (int j = 0; j < 4; j++) { kb[j] = kn[j]; vb[j] = vn[j]; rb[j] = rn[j]; }
    }
    aa_o[idx] = aa; bb_o[idx] = bb; pp_o[idx] = pp;
}

// ---------------- fp16 tensor-core GEMM (round-11 proven core, + CN stride + half EPIs) ----------------
// A: half-pair words [M][K/2]; B: packed half-pair words [K/2][N], N = logical width.
// C addressed with row stride CN (allows writing a column block of a wider buffer).
// EPI: 0=none, 1=sigmoid, 2=relu^2->half, 3=acc+X, 4=X+S*acc, 5=none->half, 6=sigmoid->half

#define CP16(d, s)  asm volatile("cp.async.cg.shared.global [%0], [%1], 16;\n" :: "r"(d), "l"(s) : "memory")
#define CPCOMMIT()  asm volatile("cp.async.commit_group;\n" ::: "memory")
#define CPWAIT1()   asm volatile("cp.async.wait_group 1;\n" ::: "memory")
#define CPWAIT0()   asm volatile("cp.async.wait_group 0;\n" ::: "memory")

__device__ __forceinline__ void mma16816(float* c, const unsigned* a, const unsigned* b) {
    asm volatile(
        "mma.sync.aligned.m16n8k16.row.col.f32.f16.f16.f32 "
        "{%0,%1,%2,%3}, {%4,%5,%6,%7}, {%8,%9}, {%0,%1,%2,%3};\n"
        : "+f"(c[0]), "+f"(c[1]), "+f"(c[2]), "+f"(c[3])
        : "r"(a[0]), "r"(a[1]), "r"(a[2]), "r"(a[3]), "r"(b[0]), "r"(b[1]));
}

#define A_STRIDE 12            // words per A smem row
#define B_STRIDE 136           // words per B smem row
#define A_STAGE_W (128 * A_STRIDE)   // 1536 words
#define B_STAGE_W (8 * B_STRIDE)     // 1088 words

template<int EPI>
__global__ void __launch_bounds__(128, 2) tgemm(
    const unsigned* __restrict__ A32, const unsigned* __restrict__ B32, void* __restrict__ Cp,
    int M, int N, int K, int CN,
    const float* __restrict__ X, const float* __restrict__ S)
{
    __shared__ __align__(16) unsigned sA[3 * A_STAGE_W];
    __shared__ __align__(16) unsigned sB[3 * B_STAGE_W];

    const int tid  = threadIdx.x;
    const int lane = tid & 31;
    const int warp = tid >> 5;      // 0..3
    const int wm   = warp >> 1;     // 0..1
    const int wn   = warp & 1;      // 0..1
    const int bm   = blockIdx.y * 128;
    const int bn   = blockIdx.x * 128;
    const int Kw   = K >> 1;

    const uint32_t aB = (uint32_t)__cvta_generic_to_shared(sA);
    const uint32_t bB = (uint32_t)__cvta_generic_to_shared(sB);

    const unsigned* aRow = A32 + (size_t)(bm + tid) * Kw;
    const uint32_t  aD   = aB + tid * (A_STRIDE * 4);
    const int bkh = tid >> 4;
    const int bc  = tid & 15;
    const unsigned* bRow = B32 + bn + (size_t)bkh * N;
    const uint32_t  bD   = bB + bkh * (B_STRIDE * 4);

    auto issue = [&](int s, int st) {
        const int k0w = s << 3;
        const unsigned* as = aRow + k0w;
        uint32_t ad = aD + st * (A_STAGE_W * 4);
        CP16(ad,      as);
        CP16(ad + 16, as + 4);
        const unsigned* bs = bRow + (size_t)k0w * N;
        uint32_t bd = bD + st * (B_STAGE_W * 4);
        CP16(bd + bc * 16,        bs + bc * 4);
        CP16(bd + (bc + 16) * 16, bs + (bc + 16) * 4);
        CPCOMMIT();
    };

    float acc[4][8][4];
#pragma unroll
    for (int i = 0; i < 4; i++)
#pragma unroll
        for (int j = 0; j < 8; j++)
#pragma unroll
            for (int e = 0; e < 4; e++) acc[i][j][e] = 0.f;

    const int aT = wm * 768 + (lane >> 2) * A_STRIDE + (lane & 3);
    const int bT = (lane & 3) * B_STRIDE + wn * 64 + (lane >> 2);

    const int ns = K >> 4;
    issue(0, 0); issue(1, 1);
    int st = 0, st2 = 2;
    for (int s = 0; s < ns; s++) {
        if (s == ns - 1) { CPWAIT0(); } else { CPWAIT1(); }
        __syncthreads();
        if (s + 2 < ns) { issue(s + 2, st2); st2 = (st2 == 2) ? 0 : st2 + 1; }

        const unsigned* Aw = sA + st * A_STAGE_W;
        const unsigned* Bw = sB + st * B_STAGE_W;
        unsigned af[4][4], bf[8][2];
#pragma unroll
        for (int mt = 0; mt < 4; mt++)
#pragma unroll
            for (int r = 0; r < 4; r++)
                af[mt][r] = Aw[aT + mt * 192 + (r & 1) * 96 + (r >> 1) * 4];
#pragma unroll
        for (int nt = 0; nt < 8; nt++)
#pragma unroll
            for (int r = 0; r < 2; r++)
                bf[nt][r] = Bw[bT + nt * 8 + r * (4 * B_STRIDE)];
#pragma unroll
        for (int mt = 0; mt < 4; mt++)
#pragma unroll
            for (int nt = 0; nt < 8; nt++)
                mma16816(acc[mt][nt], af[mt], bf[nt]);

        st = (st == 2) ? 0 : st + 1;
    }

    // ---- epilogue (C row stride = CN) ----
    float* C = (float*)Cp;
    const int rbase = bm + wm * 64 + (lane >> 2);
    const int cbase = bn + wn * 64 + ((lane & 3) << 1);
#pragma unroll
    for (int mt = 0; mt < 4; mt++) {
#pragma unroll
        for (int h = 0; h < 2; h++) {
            const int row = rbase + mt * 16 + h * 8;
#pragma unroll
            for (int nt = 0; nt < 8; nt++) {
                const int col = cbase + nt * 8;
                const size_t idx = (size_t)row * CN + col;
                float v0 = acc[mt][nt][h * 2 + 0];
                float v1 = acc[mt][nt][h * 2 + 1];
                if (EPI == 1) {
                    v0 = 1.f / (1.f + expf(-v0));
                    v1 = 1.f / (1.f + expf(-v1));
                    float2 o; o.x = v0; o.y = v1;
                    *(float2*)&C[idx] = o;
                } else if (EPI == 2) {
                    v0 = fmaxf(v0, 0.f); v0 *= v0;
                    v1 = fmaxf(v1, 0.f); v1 *= v1;
                    __half2 hh = __floats2half2_rn(v0, v1);
                    *(unsigned*)((__half*)Cp + idx) = *(unsigned*)&hh;
                } else if (EPI == 3) {
                    float2 xv = *(const float2*)&X[idx];
                    float2 o; o.x = v0 + xv.x; o.y = v1 + xv.y;
                    *(float2*)&C[idx] = o;
                } else if (EPI == 4) {
                    float2 xv = *(const float2*)&X[idx];
                    float2 sv = *(const float2*)&S[idx];
                    float2 o;
                    o.x = xv.x + sv.x * v0;
                    o.y = xv.y + sv.y * v1;
                    *(float2*)&C[idx] = o;
                } else if (EPI == 5) {
                    __half2 hh = __floats2half2_rn(v0, v1);
                    *(unsigned*)((__half*)Cp + idx) = *(unsigned*)&hh;
                } else if (EPI == 6) {
                    v0 = 1.f / (1.f + expf(-v0));
                    v1 = 1.f / (1.f + expf(-v1));
                    __half2 hh = __floats2half2_rn(v0, v1);
                    *(unsigned*)((__half*)Cp + idx) = *(unsigned*)&hh;
                } else {
                    float2 o; o.x = v0; o.y = v1;
                    *(float2*)&C[idx] = o;
                }
            }
        }
    }
}

// ---------------- host ----------------
extern "C" void kernel_launch(void* const* d_in, const int* in_sizes, int n_in,
                              void* d_out, int out_size)
{
    const float* x        = (const float*)d_in[0];
    const float* att_x    = (const float*)d_in[1];
    const float* att_a    = (const float*)d_in[2];
    const float* att_b    = (const float*)d_in[3];
    const float* att_p    = (const float*)d_in[4];
    const float* ffn_x    = (const float*)d_in[5];
    const float* ln1_g    = (const float*)d_in[6];
    const float* ln1_b    = (const float*)d_in[7];
    const float* ln2_g    = (const float*)d_in[8];
    const float* ln2_b    = (const float*)d_in[9];
    const float* tm_mix_k = (const float*)d_in[10];
    const float* tm_mix_v = (const float*)d_in[11];
    const float* tm_mix_r = (const float*)d_in[12];
    const float* tm_decay = (const float*)d_in[13];
    const float* tm_first = (const float*)d_in[14];
    const float* Wk       = (const float*)d_in[15];
    const float* Wv       = (const float*)d_in[16];
    const float* Wr       = (const float*)d_in[17];
    const float* Wo       = (const float*)d_in[18];
    const float* cm_mix_k = (const float*)d_in[19];
    const float* cm_mix_r = (const float*)d_in[20];
    const float* Ck       = (const float*)d_in[21];
    const float* Cr       = (const float*)d_in[22];
    const float* Cv       = (const float*)d_in[23];

    float* out = (float*)d_out;
    const size_t OFS_XN1 = (size_t)MM * DD;
    const size_t OFS_AA  = OFS_XN1 + (size_t)BB * DD;
    const size_t OFS_BB  = OFS_AA  + (size_t)BB * DD;
    const size_t OFS_PP  = OFS_BB  + (size_t)BB * DD;
    const size_t OFS_XN2 = OFS_PP  + (size_t)BB * DD;

    float *xn, *x1, *xn2, *rc;
    unsigned *mk, *mv, *mr, *mck, *mcr;
    __half *kvr, *rw, *kc;
    unsigned *pWk, *pWv, *pWr, *pWo, *pCr, *pCk, *pCv;
    cudaGetSymbolAddress((void**)&xn,  g_xn);
    cudaGetSymbolAddress((void**)&mk,  g_mk);
    cudaGetSymbolAddress((void**)&mv,  g_mv);
    cudaGetSymbolAddress((void**)&mr,  g_mr);
    cudaGetSymbolAddress((void**)&kvr, g_kvr);
    cudaGetSymbolAddress((void**)&rw,  g_rw);
    cudaGetSymbolAddress((void**)&x1,  g_x1);
    cudaGetSymbolAddress((void**)&xn2, g_xn2);
    cudaGetSymbolAddress((void**)&mck, g_mck);
    cudaGetSymbolAddress((void**)&mcr, g_mcr);
    cudaGetSymbolAddress((void**)&kc,  g_kc);
    cudaGetSymbolAddress((void**)&rc,  g_rc);
    cudaGetSymbolAddress((void**)&pWk, g_pWk);
    cudaGetSymbolAddress((void**)&pWv, g_pWv);
    cudaGetSymbolAddress((void**)&pWr, g_pWr);
    cudaGetSymbolAddress((void**)&pWo, g_pWo);
    cudaGetSymbolAddress((void**)&pCr, g_pCr);
    cudaGetSymbolAddress((void**)&pCk, g_pCk);
    cudaGetSymbolAddress((void**)&pCv, g_pCv);

    const int mixBlocks = (MM * D4 + 255) / 256;

    // 0) pack weights to fp16 k-pair layout
    const int pwD = ((DD / 2) * DD + 255) / 256;
    pack_w<<<pwD, 256>>>(Wk, pWk, DD, DD);
    pack_w<<<pwD, 256>>>(Wv, pWv, DD, DD);
    pack_w<<<pwD, 256>>>(Wr, pWr, DD, DD);
    pack_w<<<pwD, 256>>>(Wo, pWo, DD, DD);
    pack_w<<<pwD, 256>>>(Cr, pCr, DD, DD);
    pack_w<<<((DD / 2) * FF + 255) / 256, 256>>>(Ck, pCk, DD, FF);
    pack_w<<<((FF / 2) * DD + 255) / 256, 256>>>(Cv, pCv, FF, DD);

    // 1) ln1(x) -> xn  (+ xn_last output)
    ln_kernel<<<MM, 256>>>(x, ln1_g, ln1_b, xn, out + OFS_XN1);

    // 2) token shift + mix for k/v/r (half-packed outputs)
    mix_kernel<3><<<mixBlocks, 256>>>(xn, att_x, tm_mix_k, tm_mix_v, tm_mix_r, mk, mv, mr);

    // 3) K, V, R GEMMs -> half column blocks of the fused kvr buffer (CN = 3072)
    dim3 gD(DD / 128, MM / 128);
    tgemm<5><<<gD, 128>>>(mk, pWk, kvr,          MM, DD, DD, N3, nullptr, nullptr);
    tgemm<5><<<gD, 128>>>(mv, pWv, kvr + DD,     MM, DD, DD, N3, nullptr, nullptr);
    tgemm<6><<<gD, 128>>>(mr, pWr, kvr + 2 * DD, MM, DD, DD, N3, nullptr, nullptr);

    // 4) WKV scan (half fused input), state outputs
    wkv_kernel<<<(BB * DD) / 64, 64>>>(kvr, att_a, att_b, att_p,
                                       tm_decay, tm_first, rw,
                                       out + OFS_AA, out + OFS_BB, out + OFS_PP);

    // 5) x1 = x + (r*wkv) @ Wo
    tgemm<3><<<gD, 128>>>((const unsigned*)rw, pWo, x1, MM, DD, DD, DD, x, nullptr);

    // 6) ln2(x1) -> xn2 (+ xn2_last output)
    ln_kernel<<<MM, 256>>>(x1, ln2_g, ln2_b, xn2, out + OFS_XN2);

    // 7) channel-mix token shift (half-packed outputs)
    mix_kernel<2><<<mixBlocks, 256>>>(xn2, ffn_x, cm_mix_k, cm_mix_r, nullptr, mck, mcr, nullptr);

    // 8) kc = relu(mck @ Ck)^2 -> half   [M=8192, N=4096, K=1024]
    dim3 gF(FF / 128, MM / 128);
    tgemm<2><<<gF, 128>>>(mck, pCk, kc, MM, FF, DD, FF, nullptr, nullptr);

    // 9) rc = sigmoid(mcr @ Cr)
    tgemm<1><<<gD, 128>>>(mcr, pCr, rc, MM, DD, DD, DD, nullptr, nullptr);

    // 10) out = x1 + rc * (kc @ Cv)   [M=8192, N=1024, K=4096]
    tgemm<4><<<gD, 128>>>((const unsigned*)kc, pCv, out, MM, DD, FF, DD, x1, rc);
}

// round 14
// speedup vs baseline: 1.0448x; 1.0448x over previous
#include <cuda_runtime.h>
#include <cuda_fp16.h>
#include <cstdint>

#define BB 8
#define TT 1024
#define DD 1024
#define FF 4096
#define MM (BB*TT)          // 8192 rows
#define D4 (DD/4)

// ---------------- scratch (static device allocations; allowed) ----------------
__device__ unsigned g_mk [MM*DD/2];   // half2-packed GEMM A operands
__device__ unsigned g_mv [MM*DD/2];
__device__ unsigned g_mr [MM*DD/2];
__device__ float    g_k  [MM*DD];
__device__ float    g_v  [MM*DD];
__device__ float    g_r  [MM*DD];
__device__ __half   g_rw [MM*DD];     // r * wkv (half, GEMM A operand)
__device__ float    g_x1 [MM*DD];
__device__ unsigned g_mck[MM*DD/2];
__device__ unsigned g_mcr[MM*DD/2];
__device__ __half   g_kc [MM*FF];     // relu^2 out (half, GEMM A operand)
__device__ float    g_rc [MM*DD];
// k-pair-packed fp16 weights: word(kh,n) = {h(W[2kh][n]), h(W[2kh+1][n])}
__device__ unsigned g_pWk[(DD/2)*DD];
__device__ unsigned g_pWv[(DD/2)*DD];
__device__ unsigned g_pWr[(DD/2)*DD];
__device__ unsigned g_pWo[(DD/2)*DD];
__device__ unsigned g_pCr[(DD/2)*DD];
__device__ unsigned g_pCk[(DD/2)*FF];
__device__ unsigned g_pCv[(FF/2)*DD];

// ---------------- weight pack: fp32 [Kd][Nd] -> half2 words [Kd/2][Nd] ----------------
__global__ void __launch_bounds__(256) pack_w(
    const float* __restrict__ in, unsigned* __restrict__ out, int Kd, int Nd)
{
    const int i = blockIdx.x * blockDim.x + threadIdx.x;
    const int tot = (Kd >> 1) * Nd;
    if (i >= tot) return;
    const int kh = i / Nd, n = i - kh * Nd;
    const float lo = in[(size_t)(2 * kh)     * Nd + n];
    const float hi = in[(size_t)(2 * kh + 1) * Nd + n];
    __half2 h = __floats2half2_rn(lo, hi);
    out[i] = *(unsigned*)&h;
}

// ---------------- fused LayerNorm + token-shift mix -> half-packed GEMM operands ----------------
// One block per row. Computes LN(x[row]) and LN(x[row-1]) (or uses x0 state at t==0),
// then writes the lerp-mixed operands directly. Eliminates the xn intermediate entirely.
template<int NOUT>
__global__ void __launch_bounds__(256) ln_mix_kernel(
    const float* __restrict__ x, const float* __restrict__ g, const float* __restrict__ b,
    const float* __restrict__ x0,       // [B,D] raw shift state (used as-is at t==0)
    const float* __restrict__ m0, const float* __restrict__ m1, const float* __restrict__ m2,
    unsigned* __restrict__ o0, unsigned* __restrict__ o1, unsigned* __restrict__ o2,
    float* __restrict__ last)           // [B,D] slot for LN of row t==T-1
{
    const int row = blockIdx.x;
    const int t   = row & (TT - 1);
    const int bi  = row >> 10;          // TT == 1024
    const int tid = threadIdx.x;

    float4 xc = ((const float4*)(x + (size_t)row * DD))[tid];
    float4 xq = make_float4(0.f, 0.f, 0.f, 0.f);
    if (t > 0) xq = ((const float4*)(x + (size_t)(row - 1) * DD))[tid];

    float s0 = xc.x + xc.y + xc.z + xc.w;
    float q0 = xc.x*xc.x + xc.y*xc.y + xc.z*xc.z + xc.w*xc.w;
    float s1 = xq.x + xq.y + xq.z + xq.w;
    float q1 = xq.x*xq.x + xq.y*xq.y + xq.z*xq.z + xq.w*xq.w;
#pragma unroll
    for (int o = 16; o; o >>= 1) {
        s0 += __shfl_xor_sync(0xffffffffu, s0, o);
        q0 += __shfl_xor_sync(0xffffffffu, q0, o);
        s1 += __shfl_xor_sync(0xffffffffu, s1, o);
        q1 += __shfl_xor_sync(0xffffffffu, q1, o);
    }
    __shared__ float sh[32];
    const int w = tid >> 5, l = tid & 31;
    if (l == 0) { sh[w] = s0; sh[8 + w] = q0; sh[16 + w] = s1; sh[24 + w] = q1; }
    __syncthreads();
    s0 = 0.f; q0 = 0.f; s1 = 0.f; q1 = 0.f;
#pragma unroll
    for (int i = 0; i < 8; i++) {
        s0 += sh[i]; q0 += sh[8 + i]; s1 += sh[16 + i]; q1 += sh[24 + i];
    }
    const float mean0 = s0 * (1.0f / DD);
    const float rstd0 = rsqrtf(q0 * (1.0f / DD) - mean0 * mean0 + 1e-3f);
    const float mean1 = s1 * (1.0f / DD);
    const float rstd1 = rsqrtf(q1 * (1.0f / DD) - mean1 * mean1 + 1e-3f);

    float4 gg = ((const float4*)g)[tid];
    float4 bb = ((const float4*)b)[tid];

    float4 xnc;   // LN of current row
    xnc.x = (xc.x - mean0) * rstd0 * gg.x + bb.x;
    xnc.y = (xc.y - mean0) * rstd0 * gg.y + bb.y;
    xnc.z = (xc.z - mean0) * rstd0 * gg.z + bb.z;
    xnc.w = (xc.w - mean0) * rstd0 * gg.w + bb.w;

    float4 xnp;   // shift value: LN of prev row, or raw state at t==0
    if (t > 0) {
        xnp.x = (xq.x - mean1) * rstd1 * gg.x + bb.x;
        xnp.y = (xq.y - mean1) * rstd1 * gg.y + bb.y;
        xnp.z = (xq.z - mean1) * rstd1 * gg.z + bb.z;
        xnp.w = (xq.w - mean1) * rstd1 * gg.w + bb.w;
    } else {
        xnp = ((const float4*)(x0 + (size_t)bi * DD))[tid];
    }

    {
        float4 m = ((const float4*)m0)[tid];
        __half2 p0 = __floats2half2_rn(xnp.x + (xnc.x - xnp.x) * m.x, xnp.y + (xnc.y - xnp.y) * m.y);
        __half2 p1 = __floats2half2_rn(xnp.z + (xnc.z - xnp.z) * m.z, xnp.w + (xnc.w - xnp.w) * m.w);
        uint2 wv; wv.x = *(unsigned*)&p0; wv.y = *(unsigned*)&p1;
        ((uint2*)o0)[(size_t)row * D4 + tid] = wv;
    }
    if (NOUT >= 2) {
        float4 m = ((const float4*)m1)[tid];
        __half2 p0 = __floats2half2_rn(xnp.x + (xnc.x - xnp.x) * m.x, xnp.y + (xnc.y - xnp.y) * m.y);
        __half2 p1 = __floats2half2_rn(xnp.z + (xnc.z - xnp.z) * m.z, xnp.w + (xnc.w - xnp.w) * m.w);
        uint2 wv; wv.x = *(unsigned*)&p0; wv.y = *(unsigned*)&p1;
        ((uint2*)o1)[(size_t)row * D4 + tid] = wv;
    }
    if (NOUT >= 3) {
        float4 m = ((const float4*)m2)[tid];
        __half2 p0 = __floats2half2_rn(xnp.x + (xnc.x - xnp.x) * m.x, xnp.y + (xnc.y - xnp.y) * m.y);
        __half2 p1 = __floats2half2_rn(xnp.z + (xnc.z - xnp.z) * m.z, xnp.w + (xnc.w - xnp.w) * m.w);
        uint2 wv; wv.x = *(unsigned*)&p0; wv.y = *(unsigned*)&p1;
        ((uint2*)o2)[(size_t)row * D4 + tid] = wv;
    }
    if (t == TT - 1) {
        ((float4*)(last + (size_t)bi * DD))[tid] = xnc;
    }
}

// ---------------- WKV scan: fp32 k/v/r inputs, 4-deep prefetch, half rw out (R11) ----------------
__global__ void __launch_bounds__(64) wkv_kernel(
    const float* __restrict__ k, const float* __restrict__ v, const float* __restrict__ r,
    const float* __restrict__ a0, const float* __restrict__ b0, const float* __restrict__ p0,
    const float* __restrict__ decay, const float* __restrict__ first,
    __half* __restrict__ rw,
    float* __restrict__ aa_o, float* __restrict__ bb_o, float* __restrict__ pp_o)
{
    const int idx = blockIdx.x * blockDim.x + threadIdx.x;
    if (idx >= BB * DD) return;
    const int d = idx % DD, b = idx / DD;
    float aa = a0[idx], bb = b0[idx], pp = p0[idx];
    const float w = -expf(decay[d]);
    const float u = first[d];
    const size_t base = (size_t)b * TT * DD + d;

    float kb[4], vb[4], rb[4];
#pragma unroll
    for (int j = 0; j < 4; j++) {
        kb[j] = k[base + (size_t)j * DD];
        vb[j] = v[base + (size_t)j * DD];
        rb[j] = r[base + (size_t)j * DD];
    }

    for (int t0 = 0; t0 < TT; t0 += 4) {
        float kn[4], vn[4], rn[4];
        if (t0 + 4 < TT) {
#pragma unroll
            for (int j = 0; j < 4; j++) {
                const size_t off = base + (size_t)(t0 + 4 + j) * DD;
                kn[j] = k[off]; vn[j] = v[off]; rn[j] = r[off];
            }
        } else {
#pragma unroll
            for (int j = 0; j < 4; j++) { kn[j] = 0.f; vn[j] = 0.f; rn[j] = 0.f; }
        }
#pragma unroll
        for (int j = 0; j < 4; j++) {
            const size_t off = base + (size_t)(t0 + j) * DD;
            const float kt = kb[j], vt = vb[j], rt = rb[j];
            float ww = u + kt;
            float p  = fmaxf(pp, ww);
            float e1 = expf(pp - p), e2 = expf(ww - p);
            float wkv = (e1 * aa + e2 * vt) / (e1 * bb + e2);
            rw[off] = __float2half_rn(rt * wkv);
            float ww2 = pp + w;
            float p2  = fmaxf(ww2, kt);
            float e1b = expf(ww2 - p2), e2b = expf(kt - p2);
            aa = e1b * aa + e2b * vt;
            bb = e1b * bb + e2b;
            pp = p2;
        }
#pragma unroll
        for (int j = 0; j < 4; j++) { kb[j] = kn[j]; vb[j] = vn[j]; rb[j] = rn[j]; }
    }
    aa_o[idx] = aa; bb_o[idx] = bb; pp_o[idx] = pp;
}

// ---------------- fp16 tensor-core GEMM: 128x128x16, mma.m16n8k16, cp.async 3-stage ----------------
// (round-11 proven core, byte-identical)
// EPI: 0=none, 1=sigmoid, 2=relu^2->half, 3=acc+X, 4=X + S*acc

#define CP16(d, s)  asm volatile("cp.async.cg.shared.global [%0], [%1], 16;\n" :: "r"(d), "l"(s) : "memory")
#define CPCOMMIT()  asm volatile("cp.async.commit_group;\n" ::: "memory")
#define CPWAIT1()   asm volatile("cp.async.wait_group 1;\n" ::: "memory")
#define CPWAIT0()   asm volatile("cp.async.wait_group 0;\n" ::: "memory")

__device__ __forceinline__ void mma16816(float* c, const unsigned* a, const unsigned* b) {
    asm volatile(
        "mma.sync.aligned.m16n8k16.row.col.f32.f16.f16.f32 "
        "{%0,%1,%2,%3}, {%4,%5,%6,%7}, {%8,%9}, {%0,%1,%2,%3};\n"
        : "+f"(c[0]), "+f"(c[1]), "+f"(c[2]), "+f"(c[3])
        : "r"(a[0]), "r"(a[1]), "r"(a[2]), "r"(a[3]), "r"(b[0]), "r"(b[1]));
}

#define A_STRIDE 12            // words per A smem row
#define B_STRIDE 136           // words per B smem row
#define A_STAGE_W (128 * A_STRIDE)   // 1536 words
#define B_STAGE_W (8 * B_STRIDE)     // 1088 words

template<int EPI>
__global__ void __launch_bounds__(128, 2) tgemm(
    const unsigned* __restrict__ A32, const unsigned* __restrict__ B32, void* __restrict__ Cp,
    int M, int N, int K,
    const float* __restrict__ X, const float* __restrict__ S)
{
    __shared__ __align__(16) unsigned sA[3 * A_STAGE_W];
    __shared__ __align__(16) unsigned sB[3 * B_STAGE_W];

    const int tid  = threadIdx.x;
    const int lane = tid & 31;
    const int warp = tid >> 5;      // 0..3
    const int wm   = warp >> 1;     // 0..1
    const int wn   = warp & 1;      // 0..1
    const int bm   = blockIdx.y * 128;
    const int bn   = blockIdx.x * 128;
    const int Kw   = K >> 1;

    const uint32_t aB = (uint32_t)__cvta_generic_to_shared(sA);
    const uint32_t bB = (uint32_t)__cvta_generic_to_shared(sB);

    // producer per-thread constants
    const unsigned* aRow = A32 + (size_t)(bm + tid) * Kw;       // A row m = tid
    const uint32_t  aD   = aB + tid * (A_STRIDE * 4);
    const int bkh = tid >> 4;                                   // B smem row 0..7
    const int bc  = tid & 15;                                   // chunk base
    const unsigned* bRow = B32 + bn + (size_t)bkh * N;
    const uint32_t  bD   = bB + bkh * (B_STRIDE * 4);

    auto issue = [&](int s, int st) {
        const int k0w = s << 3;                                 // (s*16)/2
        const unsigned* as = aRow + k0w;
        uint32_t ad = aD + st * (A_STAGE_W * 4);
        CP16(ad,      as);
        CP16(ad + 16, as + 4);
        const unsigned* bs = bRow + (size_t)k0w * N;
        uint32_t bd = bD + st * (B_STAGE_W * 4);
        CP16(bd + bc * 16,        bs + bc * 4);
        CP16(bd + (bc + 16) * 16, bs + (bc + 16) * 4);
        CPCOMMIT();
    };

    float acc[4][8][4];
#pragma unroll
    for (int i = 0; i < 4; i++)
#pragma unroll
        for (int j = 0; j < 8; j++)
#pragma unroll
            for (int e = 0; e < 4; e++) acc[i][j][e] = 0.f;

    // compute-side per-thread bases (purely linear addressing)
    const int aT = wm * 768 + (lane >> 2) * A_STRIDE + (lane & 3);
    const int bT = (lane & 3) * B_STRIDE + wn * 64 + (lane >> 2);

    const int ns = K >> 4;
    issue(0, 0); issue(1, 1);
    int st = 0, st2 = 2;
    for (int s = 0; s < ns; s++) {
        if (s == ns - 1) { CPWAIT0(); } else { CPWAIT1(); }
        __syncthreads();
        if (s + 2 < ns) { issue(s + 2, st2); st2 = (st2 == 2) ? 0 : st2 + 1; }

        const unsigned* Aw = sA + st * A_STAGE_W;
        const unsigned* Bw = sB + st * B_STAGE_W;
        unsigned af[4][4], bf[8][2];
#pragma unroll
        for (int mt = 0; mt < 4; mt++)
#pragma unroll
            for (int r = 0; r < 4; r++)
                af[mt][r] = Aw[aT + mt * 192 + (r & 1) * 96 + (r >> 1) * 4];
#pragma unroll
        for (int nt = 0; nt < 8; nt++)
#pragma unroll
            for (int r = 0; r < 2; r++)
                bf[nt][r] = Bw[bT + nt * 8 + r * (4 * B_STRIDE)];
#pragma unroll
        for (int mt = 0; mt < 4; mt++)
#pragma unroll
            for (int nt = 0; nt < 8; nt++)
                mma16816(acc[mt][nt], af[mt], bf[nt]);

        st = (st == 2) ? 0 : st + 1;
    }

    // ---- epilogue ----
    float* C = (float*)Cp;
    const int rbase = bm + wm * 64 + (lane >> 2);
    const int cbase = bn + wn * 64 + ((lane & 3) << 1);
#pragma unroll
    for (int mt = 0; mt < 4; mt++) {
#pragma unroll
        for (int h = 0; h < 2; h++) {
            const int row = rbase + mt * 16 + h * 8;
#pragma unroll
            for (int nt = 0; nt < 8; nt++) {
                const int col = cbase + nt * 8;
                const size_t idx = (size_t)row * N + col;
                float v0 = acc[mt][nt][h * 2 + 0];
                float v1 = acc[mt][nt][h * 2 + 1];
                if (EPI == 1) {
                    v0 = 1.f / (1.f + expf(-v0));
                    v1 = 1.f / (1.f + expf(-v1));
                    float2 o; o.x = v0; o.y = v1;
                    *(float2*)&C[idx] = o;
                } else if (EPI == 2) {
                    v0 = fmaxf(v0, 0.f); v0 *= v0;
                    v1 = fmaxf(v1, 0.f); v1 *= v1;
                    __half2 hh = __floats2half2_rn(v0, v1);
                    ((unsigned*)Cp)[idx >> 1] = *(unsigned*)&hh;
                } else if (EPI == 3) {
                    float2 xv = *(const float2*)&X[idx];
                    float2 o; o.x = v0 + xv.x; o.y = v1 + xv.y;
                    *(float2*)&C[idx] = o;
                } else if (EPI == 4) {
                    float2 xv = *(const float2*)&X[idx];
                    float2 sv = *(const float2*)&S[idx];
                    float2 o;
                    o.x = xv.x + sv.x * v0;
                    o.y = xv.y + sv.y * v1;
                    *(float2*)&C[idx] = o;
                } else {
                    float2 o; o.x = v0; o.y = v1;
                    *(float2*)&C[idx] = o;
                }
            }
        }
    }
}

// ---------------- host ----------------
extern "C" void kernel_launch(void* const* d_in, const int* in_sizes, int n_in,
                              void* d_out, int out_size)
{
    const float* x        = (const float*)d_in[0];
    const float* att_x    = (const float*)d_in[1];
    const float* att_a    = (const float*)d_in[2];
    const float* att_b    = (const float*)d_in[3];
    const float* att_p    = (const float*)d_in[4];
    const float* ffn_x    = (const float*)d_in[5];
    const float* ln1_g    = (const float*)d_in[6];
    const float* ln1_b    = (const float*)d_in[7];
    const float* ln2_g    = (const float*)d_in[8];
    const float* ln2_b    = (const float*)d_in[9];
    const float* tm_mix_k = (const float*)d_in[10];
    const float* tm_mix_v = (const float*)d_in[11];
    const float* tm_mix_r = (const float*)d_in[12];
    const float* tm_decay = (const float*)d_in[13];
    const float* tm_first = (const float*)d_in[14];
    const float* Wk       = (const float*)d_in[15];
    const float* Wv       = (const float*)d_in[16];
    const float* Wr       = (const float*)d_in[17];
    const float* Wo       = (const float*)d_in[18];
    const float* cm_mix_k = (const float*)d_in[19];
    const float* cm_mix_r = (const float*)d_in[20];
    const float* Ck       = (const float*)d_in[21];
    const float* Cr       = (const float*)d_in[22];
    const float* Cv       = (const float*)d_in[23];

    float* out = (float*)d_out;
    const size_t OFS_XN1 = (size_t)MM * DD;
    const size_t OFS_AA  = OFS_XN1 + (size_t)BB * DD;
    const size_t OFS_BB  = OFS_AA  + (size_t)BB * DD;
    const size_t OFS_PP  = OFS_BB  + (size_t)BB * DD;
    const size_t OFS_XN2 = OFS_PP  + (size_t)BB * DD;

    float *kk, *vv, *rr, *x1, *rc;
    unsigned *mk, *mv, *mr, *mck, *mcr;
    __half *rw, *kc;
    unsigned *pWk, *pWv, *pWr, *pWo, *pCr, *pCk, *pCv;
    cudaGetSymbolAddress((void**)&mk,  g_mk);
    cudaGetSymbolAddress((void**)&mv,  g_mv);
    cudaGetSymbolAddress((void**)&mr,  g_mr);
    cudaGetSymbolAddress((void**)&kk,  g_k);
    cudaGetSymbolAddress((void**)&vv,  g_v);
    cudaGetSymbolAddress((void**)&rr,  g_r);
    cudaGetSymbolAddress((void**)&rw,  g_rw);
    cudaGetSymbolAddress((void**)&x1,  g_x1);
    cudaGetSymbolAddress((void**)&mck, g_mck);
    cudaGetSymbolAddress((void**)&mcr, g_mcr);
    cudaGetSymbolAddress((void**)&kc,  g_kc);
    cudaGetSymbolAddress((void**)&rc,  g_rc);
    cudaGetSymbolAddress((void**)&pWk, g_pWk);
    cudaGetSymbolAddress((void**)&pWv, g_pWv);
    cudaGetSymbolAddress((void**)&pWr, g_pWr);
    cudaGetSymbolAddress((void**)&pWo, g_pWo);
    cudaGetSymbolAddress((void**)&pCr, g_pCr);
    cudaGetSymbolAddress((void**)&pCk, g_pCk);
    cudaGetSymbolAddress((void**)&pCv, g_pCv);

    // 0) pack weights to fp16 k-pair layout
    const int pwD = ((DD / 2) * DD + 255) / 256;
    pack_w<<<pwD, 256>>>(Wk, pWk, DD, DD);
    pack_w<<<pwD, 256>>>(Wv, pWv, DD, DD);
    pack_w<<<pwD, 256>>>(Wr, pWr, DD, DD);
    pack_w<<<pwD, 256>>>(Wo, pWo, DD, DD);
    pack_w<<<pwD, 256>>>(Cr, pCr, DD, DD);
    pack_w<<<((DD / 2) * FF + 255) / 256, 256>>>(Ck, pCk, DD, FF);
    pack_w<<<((FF / 2) * DD + 255) / 256, 256>>>(Cv, pCv, FF, DD);

    // 1+2) fused ln1 + time-mix -> mk/mv/mr (half-packed) + xn_last
    ln_mix_kernel<3><<<MM, 256>>>(x, ln1_g, ln1_b, att_x,
                                  tm_mix_k, tm_mix_v, tm_mix_r,
                                  mk, mv, mr, out + OFS_XN1);

    // 3) K, V, R GEMMs (fp32 outputs; R fused sigmoid)
    dim3 gD(DD / 128, MM / 128);
    tgemm<0><<<gD, 128>>>(mk, pWk, kk, MM, DD, DD, nullptr, nullptr);
    tgemm<0><<<gD, 128>>>(mv, pWv, vv, MM, DD, DD, nullptr, nullptr);
    tgemm<1><<<gD, 128>>>(mr, pWr, rr, MM, DD, DD, nullptr, nullptr);

    // 4) WKV scan (fp32 inputs, fused r*wkv -> half), state outputs
    wkv_kernel<<<(BB * DD) / 64, 64>>>(kk, vv, rr, att_a, att_b, att_p,
                                       tm_decay, tm_first, rw,
                                       out + OFS_AA, out + OFS_BB, out + OFS_PP);

    // 5) x1 = x + (r*wkv) @ Wo
    tgemm<3><<<gD, 128>>>((const unsigned*)rw, pWo, x1, MM, DD, DD, x, nullptr);

    // 6+7) fused ln2 + channel-mix -> mck/mcr (half-packed) + xn2_last
    ln_mix_kernel<2><<<MM, 256>>>(x1, ln2_g, ln2_b, ffn_x,
                                  cm_mix_k, cm_mix_r, nullptr,
                                  mck, mcr, nullptr, out + OFS_XN2);

    // 8) kc = relu(mck @ Ck)^2 -> half   [M=8192, N=4096, K=1024]
    dim3 gF(FF / 128, MM / 128);
    tgemm<2><<<gF, 128>>>(mck, pCk, kc, MM, FF, DD, nullptr, nullptr);

    // 9) rc = sigmoid(mcr @ Cr)
    tgemm<1><<<gD, 128>>>(mcr, pCr, rc, MM, DD, DD, nullptr, nullptr);

    // 10) out = x1 + rc * (kc @ Cv)   [M=8192, N=1024, K=4096]
    tgemm<4><<<gD, 128>>>((const unsigned*)kc, pCv, out, MM, DD, FF, x1, rc);
}

// round 15
// speedup vs baseline: 1.0994x; 1.0522x over previous
#include <cuda_runtime.h>
#include <cuda_fp16.h>
#include <cstdint>

#define BB 8
#define TT 1024
#define DD 1024
#define FF 4096
#define MM (BB*TT)          // 8192 rows
#define D4 (DD/4)

// ---------------- scratch (static device allocations; allowed) ----------------
__device__ unsigned g_mk [MM*DD/2];   // half2-packed GEMM A operands
__device__ unsigned g_mv [MM*DD/2];
__device__ unsigned g_mr [MM*DD/2];
__device__ float    g_k  [MM*DD];
__device__ float    g_v  [MM*DD];
__device__ float    g_r  [MM*DD];
__device__ __half   g_rw [MM*DD];     // r * wkv (half, GEMM A operand)
__device__ float    g_x1 [MM*DD];
__device__ unsigned g_mck[MM*DD/2];
__device__ unsigned g_mcr[MM*DD/2];
__device__ __half   g_kc [MM*FF];     // relu^2 out (half, GEMM A operand)
__device__ float    g_rc [MM*DD];
// k-pair-packed fp16 weights: word(kh,n) = {h(W[2kh][n]), h(W[2kh+1][n])}
__device__ unsigned g_pWk[(DD/2)*DD];
__device__ unsigned g_pWv[(DD/2)*DD];
__device__ unsigned g_pWr[(DD/2)*DD];
__device__ unsigned g_pWo[(DD/2)*DD];
__device__ unsigned g_pCr[(DD/2)*DD];
__device__ unsigned g_pCk[(DD/2)*FF];
__device__ unsigned g_pCv[(FF/2)*DD];

// ---------------- fused weight pack: all 7 matrices in ONE launch ----------------
// Region block counts (256 thr, 1 word/thr):
//  Wk,Wv,Wr,Wo,Cr: 2048 blocks each; Ck: 8192; Cv: 8192. Total 26624.
__global__ void __launch_bounds__(256) pack_all(
    const float* __restrict__ Wk, const float* __restrict__ Wv, const float* __restrict__ Wr,
    const float* __restrict__ Wo, const float* __restrict__ Cr,
    const float* __restrict__ Ck, const float* __restrict__ Cv,
    unsigned* __restrict__ pWk, unsigned* __restrict__ pWv, unsigned* __restrict__ pWr,
    unsigned* __restrict__ pWo, unsigned* __restrict__ pCr,
    unsigned* __restrict__ pCk, unsigned* __restrict__ pCv)
{
    int blk = blockIdx.x;
    const float* in; unsigned* out; int Nd;
    if      (blk <  2048) { in = Wk; out = pWk; Nd = DD; }
    else if (blk <  4096) { in = Wv; out = pWv; Nd = DD; blk -= 2048; }
    else if (blk <  6144) { in = Wr; out = pWr; Nd = DD; blk -= 4096; }
    else if (blk <  8192) { in = Wo; out = pWo; Nd = DD; blk -= 6144; }
    else if (blk < 10240) { in = Cr; out = pCr; Nd = DD; blk -= 8192; }
    else if (blk < 18432) { in = Ck; out = pCk; Nd = FF; blk -= 10240; }
    else                  { in = Cv; out = pCv; Nd = DD; blk -= 18432; }
    const int i = blk * 256 + threadIdx.x;
    const int kh = i / Nd, n = i - kh * Nd;
    const float lo = in[(size_t)(2 * kh)     * Nd + n];
    const float hi = in[(size_t)(2 * kh + 1) * Nd + n];
    __half2 h = __floats2half2_rn(lo, hi);
    out[i] = *(unsigned*)&h;
}

// ---------------- fused LayerNorm + token-shift mix -> half-packed GEMM operands ----------------
template<int NOUT>
__global__ void __launch_bounds__(256) ln_mix_kernel(
    const float* __restrict__ x, const float* __restrict__ g, const float* __restrict__ b,
    const float* __restrict__ x0,
    const float* __restrict__ m0, const float* __restrict__ m1, const float* __restrict__ m2,
    unsigned* __restrict__ o0, unsigned* __restrict__ o1, unsigned* __restrict__ o2,
    float* __restrict__ last)
{
    const int row = blockIdx.x;
    const int t   = row & (TT - 1);
    const int bi  = row >> 10;
    const int tid = threadIdx.x;

    float4 xc = ((const float4*)(x + (size_t)row * DD))[tid];
    float4 xq = make_float4(0.f, 0.f, 0.f, 0.f);
    if (t > 0) xq = ((const float4*)(x + (size_t)(row - 1) * DD))[tid];

    float s0 = xc.x + xc.y + xc.z + xc.w;
    float q0 = xc.x*xc.x + xc.y*xc.y + xc.z*xc.z + xc.w*xc.w;
    float s1 = xq.x + xq.y + xq.z + xq.w;
    float q1 = xq.x*xq.x + xq.y*xq.y + xq.z*xq.z + xq.w*xq.w;
#pragma unroll
    for (int o = 16; o; o >>= 1) {
        s0 += __shfl_xor_sync(0xffffffffu, s0, o);
        q0 += __shfl_xor_sync(0xffffffffu, q0, o);
        s1 += __shfl_xor_sync(0xffffffffu, s1, o);
        q1 += __shfl_xor_sync(0xffffffffu, q1, o);
    }
    __shared__ float sh[32];
    const int w = tid >> 5, l = tid & 31;
    if (l == 0) { sh[w] = s0; sh[8 + w] = q0; sh[16 + w] = s1; sh[24 + w] = q1; }
    __syncthreads();
    s0 = 0.f; q0 = 0.f; s1 = 0.f; q1 = 0.f;
#pragma unroll
    for (int i = 0; i < 8; i++) {
        s0 += sh[i]; q0 += sh[8 + i]; s1 += sh[16 + i]; q1 += sh[24 + i];
    }
    const float mean0 = s0 * (1.0f / DD);
    const float rstd0 = rsqrtf(q0 * (1.0f / DD) - mean0 * mean0 + 1e-3f);
    const float mean1 = s1 * (1.0f / DD);
    const float rstd1 = rsqrtf(q1 * (1.0f / DD) - mean1 * mean1 + 1e-3f);

    float4 gg = ((const float4*)g)[tid];
    float4 bb = ((const float4*)b)[tid];

    float4 xnc;
    xnc.x = (xc.x - mean0) * rstd0 * gg.x + bb.x;
    xnc.y = (xc.y - mean0) * rstd0 * gg.y + bb.y;
    xnc.z = (xc.z - mean0) * rstd0 * gg.z + bb.z;
    xnc.w = (xc.w - mean0) * rstd0 * gg.w + bb.w;

    float4 xnp;
    if (t > 0) {
        xnp.x = (xq.x - mean1) * rstd1 * gg.x + bb.x;
        xnp.y = (xq.y - mean1) * rstd1 * gg.y + bb.y;
        xnp.z = (xq.z - mean1) * rstd1 * gg.z + bb.z;
        xnp.w = (xq.w - mean1) * rstd1 * gg.w + bb.w;
    } else {
        xnp = ((const float4*)(x0 + (size_t)bi * DD))[tid];
    }

    {
        float4 m = ((const float4*)m0)[tid];
        __half2 p0 = __floats2half2_rn(xnp.x + (xnc.x - xnp.x) * m.x, xnp.y + (xnc.y - xnp.y) * m.y);
        __half2 p1 = __floats2half2_rn(xnp.z + (xnc.z - xnp.z) * m.z, xnp.w + (xnc.w - xnp.w) * m.w);
        uint2 wv; wv.x = *(unsigned*)&p0; wv.y = *(unsigned*)&p1;
        ((uint2*)o0)[(size_t)row * D4 + tid] = wv;
    }
    if (NOUT >= 2) {
        float4 m = ((const float4*)m1)[tid];
        __half2 p0 = __floats2half2_rn(xnp.x + (xnc.x - xnp.x) * m.x, xnp.y + (xnc.y - xnp.y) * m.y);
        __half2 p1 = __floats2half2_rn(xnp.z + (xnc.z - xnp.z) * m.z, xnp.w + (xnc.w - xnp.w) * m.w);
        uint2 wv; wv.x = *(unsigned*)&p0; wv.y = *(unsigned*)&p1;
        ((uint2*)o1)[(size_t)row * D4 + tid] = wv;
    }
    if (NOUT >= 3) {
        float4 m = ((const float4*)m2)[tid];
        __half2 p0 = __floats2half2_rn(xnp.x + (xnc.x - xnp.x) * m.x, xnp.y + (xnc.y - xnp.y) * m.y);
        __half2 p1 = __floats2half2_rn(xnp.z + (xnc.z - xnp.z) * m.z, xnp.w + (xnc.w - xnp.w) * m.w);
        uint2 wv; wv.x = *(unsigned*)&p0; wv.y = *(unsigned*)&p1;
        ((uint2*)o2)[(size_t)row * D4 + tid] = wv;
    }
    if (t == TT - 1) {
        ((float4*)(last + (size_t)bi * DD))[tid] = xnc;
    }
}

// ---------------- WKV scan: fp32 k/v/r inputs, 4-deep prefetch, half rw out ----------------
__global__ void __launch_bounds__(64) wkv_kernel(
    const float* __restrict__ k, const float* __restrict__ v, const float* __restrict__ r,
    const float* __restrict__ a0, const float* __restrict__ b0, const float* __restrict__ p0,
    const float* __restrict__ decay, const float* __restrict__ first,
    __half* __restrict__ rw,
    float* __restrict__ aa_o, float* __restrict__ bb_o, float* __restrict__ pp_o)
{
    const int idx = blockIdx.x * blockDim.x + threadIdx.x;
    if (idx >= BB * DD) return;
    const int d = idx % DD, b = idx / DD;
    float aa = a0[idx], bb = b0[idx], pp = p0[idx];
    const float w = -expf(decay[d]);
    const float u = first[d];
    const size_t base = (size_t)b * TT * DD + d;

    float kb[4], vb[4], rb[4];
#pragma unroll
    for (int j = 0; j < 4; j++) {
        kb[j] = k[base + (size_t)j * DD];
        vb[j] = v[base + (size_t)j * DD];
        rb[j] = r[base + (size_t)j * DD];
    }

    for (int t0 = 0; t0 < TT; t0 += 4) {
        float kn[4], vn[4], rn[4];
        if (t0 + 4 < TT) {
#pragma unroll
            for (int j = 0; j < 4; j++) {
                const size_t off = base + (size_t)(t0 + 4 + j) * DD;
                kn[j] = k[off]; vn[j] = v[off]; rn[j] = r[off];
            }
        } else {
#pragma unroll
            for (int j = 0; j < 4; j++) { kn[j] = 0.f; vn[j] = 0.f; rn[j] = 0.f; }
        }
#pragma unroll
        for (int j = 0; j < 4; j++) {
            const size_t off = base + (size_t)(t0 + j) * DD;
            const float kt = kb[j], vt = vb[j], rt = rb[j];
            float ww = u + kt;
            float p  = fmaxf(pp, ww);
            float e1 = expf(pp - p), e2 = expf(ww - p);
            float wkv = (e1 * aa + e2 * vt) / (e1 * bb + e2);
            rw[off] = __float2half_rn(rt * wkv);
            float ww2 = pp + w;
            float p2  = fmaxf(ww2, kt);
            float e1b = expf(ww2 - p2), e2b = expf(kt - p2);
            aa = e1b * aa + e2b * vt;
            bb = e1b * bb + e2b;
            pp = p2;
        }
#pragma unroll
        for (int j = 0; j < 4; j++) { kb[j] = kn[j]; vb[j] = vn[j]; rb[j] = rn[j]; }
    }
    aa_o[idx] = aa; bb_o[idx] = bb; pp_o[idx] = pp;
}

// ---------------- fp16 tensor-core GEMM: 128x128x16, mma.m16n8k16, cp.async 3-stage ----------------
// Inner loop byte-identical to the proven R11 core. CTA-uniform operand selection for fused modes.
// EPI: 1=sigmoid, 2=relu^2->half, 3=acc+X, 4=X+S*acc,
//      7=KVR fused (z selects {A,B,C}; sigmoid iff z==2; fp32 out),
//      8=CM pair  (bx<32: relu^2->half N=4096; bx>=32: sigmoid fp32 N=1024)

#define CP16(d, s)  asm volatile("cp.async.cg.shared.global [%0], [%1], 16;\n" :: "r"(d), "l"(s) : "memory")
#define CPCOMMIT()  asm volatile("cp.async.commit_group;\n" ::: "memory")
#define CPWAIT1()   asm volatile("cp.async.wait_group 1;\n" ::: "memory")
#define CPWAIT0()   asm volatile("cp.async.wait_group 0;\n" ::: "memory")

__device__ __forceinline__ void mma16816(float* c, const unsigned* a, const unsigned* b) {
    asm volatile(
        "mma.sync.aligned.m16n8k16.row.col.f32.f16.f16.f32 "
        "{%0,%1,%2,%3}, {%4,%5,%6,%7}, {%8,%9}, {%0,%1,%2,%3};\n"
        : "+f"(c[0]), "+f"(c[1]), "+f"(c[2]), "+f"(c[3])
        : "r"(a[0]), "r"(a[1]), "r"(a[2]), "r"(a[3]), "r"(b[0]), "r"(b[1]));
}

#define A_STRIDE 12
#define B_STRIDE 136
#define A_STAGE_W (128 * A_STRIDE)
#define B_STAGE_W (8 * B_STRIDE)

template<int EPI>
__global__ void __launch_bounds__(128, 2) tgemm(
    const unsigned* __restrict__ A32, const unsigned* __restrict__ B32, void* __restrict__ Cp,
    int M, int N, int K,
    const float* __restrict__ X, const float* __restrict__ S,
    const unsigned* A2, const unsigned* B2, void* C2,
    const unsigned* A3, const unsigned* B3, void* C3)
{
    __shared__ __align__(16) unsigned sA[3 * A_STAGE_W];
    __shared__ __align__(16) unsigned sB[3 * B_STAGE_W];

    const int tid  = threadIdx.x;
    const int lane = tid & 31;
    const int warp = tid >> 5;
    const int wm   = warp >> 1;
    const int wn   = warp & 1;
    const int bm   = blockIdx.y * 128;
    int bn = blockIdx.x * 128;

    // ---- CTA-uniform operand selection for fused modes ----
    const unsigned* Ause = A32;
    const unsigned* Buse = B32;
    void* Cuse = Cp;
    bool doSig = false;     // EPI7: sigmoid for z==2; EPI8: sigmoid for Cr half of grid
    bool crMode = false;    // EPI8: true for the Cr (N=1024, fp32) CTAs
    if (EPI == 7) {
        const int z = blockIdx.z;
        if (z == 1)      { Ause = A2; Buse = B2; Cuse = C2; }
        else if (z == 2) { Ause = A3; Buse = B3; Cuse = C3; doSig = true; }
    } else if (EPI == 8) {
        if (blockIdx.x >= 32) {
            Ause = A2; Buse = B2; Cuse = C2;
            N = DD;
            bn = (blockIdx.x - 32) * 128;
            crMode = true; doSig = true;
        }
    }
    const int Kw = K >> 1;

    const uint32_t aB = (uint32_t)__cvta_generic_to_shared(sA);
    const uint32_t bB = (uint32_t)__cvta_generic_to_shared(sB);

    const unsigned* aRow = Ause + (size_t)(bm + tid) * Kw;
    const uint32_t  aD   = aB + tid * (A_STRIDE * 4);
    const int bkh = tid >> 4;
    const int bc  = tid & 15;
    const unsigned* bRow = Buse + bn + (size_t)bkh * N;
    const uint32_t  bD   = bB + bkh * (B_STRIDE * 4);

    auto issue = [&](int s, int st) {
        const int k0w = s << 3;
        const unsigned* as = aRow + k0w;
        uint32_t ad = aD + st * (A_STAGE_W * 4);
        CP16(ad,      as);
        CP16(ad + 16, as + 4);
        const unsigned* bs = bRow + (size_t)k0w * N;
        uint32_t bd = bD + st * (B_STAGE_W * 4);
        CP16(bd + bc * 16,        bs + bc * 4);
        CP16(bd + (bc + 16) * 16, bs + (bc + 16) * 4);
        CPCOMMIT();
    };

    float acc[4][8][4];
#pragma unroll
    for (int i = 0; i < 4; i++)
#pragma unroll
        for (int j = 0; j < 8; j++)
#pragma unroll
            for (int e = 0; e < 4; e++) acc[i][j][e] = 0.f;

    const int aT = wm * 768 + (lane >> 2) * A_STRIDE + (lane & 3);
    const int bT = (lane & 3) * B_STRIDE + wn * 64 + (lane >> 2);

    const int ns = K >> 4;
    issue(0, 0); issue(1, 1);
    int st = 0, st2 = 2;
    for (int s = 0; s < ns; s++) {
        if (s == ns - 1) { CPWAIT0(); } else { CPWAIT1(); }
        __syncthreads();
        if (s + 2 < ns) { issue(s + 2, st2); st2 = (st2 == 2) ? 0 : st2 + 1; }

        const unsigned* Aw = sA + st * A_STAGE_W;
        const unsigned* Bw = sB + st * B_STAGE_W;
        unsigned af[4][4], bf[8][2];
#pragma unroll
        for (int mt = 0; mt < 4; mt++)
#pragma unroll
            for (int r = 0; r < 4; r++)
                af[mt][r] = Aw[aT + mt * 192 + (r & 1) * 96 + (r >> 1) * 4];
#pragma unroll
        for (int nt = 0; nt < 8; nt++)
#pragma unroll
            for (int r = 0; r < 2; r++)
                bf[nt][r] = Bw[bT + nt * 8 + r * (4 * B_STRIDE)];
#pragma unroll
        for (int mt = 0; mt < 4; mt++)
#pragma unroll
            for (int nt = 0; nt < 8; nt++)
                mma16816(acc[mt][nt], af[mt], bf[nt]);

        st = (st == 2) ? 0 : st + 1;
    }

    // ---- epilogue ----
    float* C = (float*)Cuse;
    const int rbase = bm + wm * 64 + (lane >> 2);
    const int cbase = bn + wn * 64 + ((lane & 3) << 1);
#pragma unroll
    for (int mt = 0; mt < 4; mt++) {
#pragma unroll
        for (int h = 0; h < 2; h++) {
            const int row = rbase + mt * 16 + h * 8;
#pragma unroll
            for (int nt = 0; nt < 8; nt++) {
                const int col = cbase + nt * 8;
                const size_t idx = (size_t)row * N + col;
                float v0 = acc[mt][nt][h * 2 + 0];
                float v1 = acc[mt][nt][h * 2 + 1];
                if (EPI == 1) {
                    v0 = 1.f / (1.f + expf(-v0));
                    v1 = 1.f / (1.f + expf(-v1));
                    float2 o; o.x = v0; o.y = v1;
                    *(float2*)&C[idx] = o;
                } else if (EPI == 2) {
                    v0 = fmaxf(v0, 0.f); v0 *= v0;
                    v1 = fmaxf(v1, 0.f); v1 *= v1;
                    __half2 hh = __floats2half2_rn(v0, v1);
                    *(unsigned*)((__half*)Cuse + idx) = *(unsigned*)&hh;
                } else if (EPI == 3) {
                    float2 xv = *(const float2*)&X[idx];
                    float2 o; o.x = v0 + xv.x; o.y = v1 + xv.y;
                    *(float2*)&C[idx] = o;
                } else if (EPI == 4) {
                    float2 xv = *(const float2*)&X[idx];
                    float2 sv = *(const float2*)&S[idx];
                    float2 o;
                    o.x = xv.x + sv.x * v0;
                    o.y = xv.y + sv.y * v1;
                    *(float2*)&C[idx] = o;
                } else if (EPI == 7) {
                    if (doSig) {
                        v0 = 1.f / (1.f + expf(-v0));
                        v1 = 1.f / (1.f + expf(-v1));
                    }
                    float2 o; o.x = v0; o.y = v1;
                    *(float2*)&C[idx] = o;
                } else if (EPI == 8) {
                    if (crMode) {
                        v0 = 1.f / (1.f + expf(-v0));
                        v1 = 1.f / (1.f + expf(-v1));
                        float2 o; o.x = v0; o.y = v1;
                        *(float2*)&C[idx] = o;
                    } else {
                        v0 = fmaxf(v0, 0.f); v0 *= v0;
                        v1 = fmaxf(v1, 0.f); v1 *= v1;
                        __half2 hh = __floats2half2_rn(v0, v1);
                        *(unsigned*)((__half*)Cuse + idx) = *(unsigned*)&hh;
                    }
                } else {
                    float2 o; o.x = v0; o.y = v1;
                    *(float2*)&C[idx] = o;
                }
            }
        }
    }
}

// ---------------- host ----------------
extern "C" void kernel_launch(void* const* d_in, const int* in_sizes, int n_in,
                              void* d_out, int out_size)
{
    const float* x        = (const float*)d_in[0];
    const float* att_x    = (const float*)d_in[1];
    const float* att_a    = (const float*)d_in[2];
    const float* att_b    = (const float*)d_in[3];
    const float* att_p    = (const float*)d_in[4];
    const float* ffn_x    = (const float*)d_in[5];
    const float* ln1_g    = (const float*)d_in[6];
    const float* ln1_b    = (const float*)d_in[7];
    const float* ln2_g    = (const float*)d_in[8];
    const float* ln2_b    = (const float*)d_in[9];
    const float* tm_mix_k = (const float*)d_in[10];
    const float* tm_mix_v = (const float*)d_in[11];
    const float* tm_mix_r = (const float*)d_in[12];
    const float* tm_decay = (const float*)d_in[13];
    const float* tm_first = (const float*)d_in[14];
    const float* Wk       = (const float*)d_in[15];
    const float* Wv       = (const float*)d_in[16];
    const float* Wr       = (const float*)d_in[17];
    const float* Wo       = (const float*)d_in[18];
    const float* cm_mix_k = (const float*)d_in[19];
    const float* cm_mix_r = (const float*)d_in[20];
    const float* Ck       = (const float*)d_in[21];
    const float* Cr       = (const float*)d_in[22];
    const float* Cv       = (const float*)d_in[23];

    float* out = (float*)d_out;
    const size_t OFS_XN1 = (size_t)MM * DD;
    const size_t OFS_AA  = OFS_XN1 + (size_t)BB * DD;
    const size_t OFS_BB  = OFS_AA  + (size_t)BB * DD;
    const size_t OFS_PP  = OFS_BB  + (size_t)BB * DD;
    const size_t OFS_XN2 = OFS_PP  + (size_t)BB * DD;

    float *kk, *vv, *rr, *x1, *rc;
    unsigned *mk, *mv, *mr, *mck, *mcr;
    __half *rw, *kc;
    unsigned *pWk, *pWv, *pWr, *pWo, *pCr, *pCk, *pCv;
    cudaGetSymbolAddress((void**)&mk,  g_mk);
    cudaGetSymbolAddress((void**)&mv,  g_mv);
    cudaGetSymbolAddress((void**)&mr,  g_mr);
    cudaGetSymbolAddress((void**)&kk,  g_k);
    cudaGetSymbolAddress((void**)&vv,  g_v);
    cudaGetSymbolAddress((void**)&rr,  g_r);
    cudaGetSymbolAddress((void**)&rw,  g_rw);
    cudaGetSymbolAddress((void**)&x1,  g_x1);
    cudaGetSymbolAddress((void**)&mck, g_mck);
    cudaGetSymbolAddress((void**)&mcr, g_mcr);
    cudaGetSymbolAddress((void**)&kc,  g_kc);
    cudaGetSymbolAddress((void**)&rc,  g_rc);
    cudaGetSymbolAddress((void**)&pWk, g_pWk);
    cudaGetSymbolAddress((void**)&pWv, g_pWv);
    cudaGetSymbolAddress((void**)&pWr, g_pWr);
    cudaGetSymbolAddress((void**)&pWo, g_pWo);
    cudaGetSymbolAddress((void**)&pCr, g_pCr);
    cudaGetSymbolAddress((void**)&pCk, g_pCk);
    cudaGetSymbolAddress((void**)&pCv, g_pCv);

    // 0) pack all 7 weights in one launch (26624 blocks)
    pack_all<<<26624, 256>>>(Wk, Wv, Wr, Wo, Cr, Ck, Cv,
                             pWk, pWv, pWr, pWo, pCr, pCk, pCv);

    // 1+2) fused ln1 + time-mix -> mk/mv/mr (half-packed) + xn_last
    ln_mix_kernel<3><<<MM, 256>>>(x, ln1_g, ln1_b, att_x,
                                  tm_mix_k, tm_mix_v, tm_mix_r,
                                  mk, mv, mr, out + OFS_XN1);

    // 3) fused K|V|R GEMMs: one launch, grid.z in {0,1,2} (sigmoid on z==2)
    dim3 gKVR(DD / 128, MM / 128, 3);
    tgemm<7><<<gKVR, 128>>>(mk, pWk, kk, MM, DD, DD, nullptr, nullptr,
                            mv, pWv, vv, mr, pWr, rr);

    // 4) WKV scan (fp32 inputs, fused r*wkv -> half), state outputs
    wkv_kernel<<<(BB * DD) / 64, 64>>>(kk, vv, rr, att_a, att_b, att_p,
                                       tm_decay, tm_first, rw,
                                       out + OFS_AA, out + OFS_BB, out + OFS_PP);

    // 5) x1 = x + (r*wkv) @ Wo
    dim3 gD(DD / 128, MM / 128);
    tgemm<3><<<gD, 128>>>((const unsigned*)rw, pWo, x1, MM, DD, DD, x, nullptr,
                          nullptr, nullptr, nullptr, nullptr, nullptr, nullptr);

    // 6+7) fused ln2 + channel-mix -> mck/mcr (half-packed) + xn2_last
    ln_mix_kernel<2><<<MM, 256>>>(x1, ln2_g, ln2_b, ffn_x,
                                  cm_mix_k, cm_mix_r, nullptr,
                                  mck, mcr, nullptr, out + OFS_XN2);

    // 8+9) fused: kc = relu(mck @ Ck)^2 -> half  AND  rc = sigmoid(mcr @ Cr)
    //      grid.x 0..31 -> Ck tiles (N=4096); 32..39 -> Cr tiles (N=1024)
    dim3 gCM(40, MM / 128);
    tgemm<8><<<gCM, 128>>>(mck, pCk, kc, MM, FF, DD, nullptr, nullptr,
                           mcr, pCr, rc, nullptr, nullptr, nullptr);

    // 10) out = x1 + rc * (kc @ Cv)   [M=8192, N=1024, K=4096]
    tgemm<4><<<gD, 128>>>((const unsigned*)kc, pCv, out, MM, DD, FF, x1, rc,
                          nullptr, nullptr, nullptr, nullptr, nullptr, nullptr);
}

// round 16
// speedup vs baseline: 1.1653x; 1.0600x over previous
#include <cuda_runtime.h>
#include <cuda_fp16.h>
#include <cstdint>

#define BB 8
#define TT 1024
#define DD 1024
#define FF 4096
#define MM (BB*TT)          // 8192 rows
#define D4 (DD/4)

// ---------------- scratch (static device allocations; allowed) ----------------
__device__ unsigned g_mk [MM*DD/2];   // half2-packed GEMM A operands
__device__ unsigned g_mv [MM*DD/2];
__device__ unsigned g_mr [MM*DD/2];
__device__ __half   g_k  [MM*DD];     // KVR GEMM outputs (half)
__device__ __half   g_v  [MM*DD];
__device__ __half   g_r  [MM*DD];
__device__ __half   g_rw [MM*DD];     // r * wkv (half, GEMM A operand)
__device__ float    g_x1 [MM*DD];
__device__ unsigned g_mck[MM*DD/2];
__device__ unsigned g_mcr[MM*DD/2];
__device__ __half   g_kc [MM*FF];     // relu^2 out (half, GEMM A operand)
__device__ float    g_rc [MM*DD];
// k-pair-packed fp16 weights: word(kh,n) = {h(W[2kh][n]), h(W[2kh+1][n])}
__device__ unsigned g_pWk[(DD/2)*DD];
__device__ unsigned g_pWv[(DD/2)*DD];
__device__ unsigned g_pWr[(DD/2)*DD];
__device__ unsigned g_pWo[(DD/2)*DD];
__device__ unsigned g_pCr[(DD/2)*DD];
__device__ unsigned g_pCk[(DD/2)*FF];
__device__ unsigned g_pCv[(FF/2)*DD];

// ---------------- fused weight pack: all 7 matrices in ONE launch ----------------
__global__ void __launch_bounds__(256) pack_all(
    const float* __restrict__ Wk, const float* __restrict__ Wv, const float* __restrict__ Wr,
    const float* __restrict__ Wo, const float* __restrict__ Cr,
    const float* __restrict__ Ck, const float* __restrict__ Cv,
    unsigned* __restrict__ pWk, unsigned* __restrict__ pWv, unsigned* __restrict__ pWr,
    unsigned* __restrict__ pWo, unsigned* __restrict__ pCr,
    unsigned* __restrict__ pCk, unsigned* __restrict__ pCv)
{
    int blk = blockIdx.x;
    const float* in; unsigned* out; int Nd;
    if      (blk <  2048) { in = Wk; out = pWk; Nd = DD; }
    else if (blk <  4096) { in = Wv; out = pWv; Nd = DD; blk -= 2048; }
    else if (blk <  6144) { in = Wr; out = pWr; Nd = DD; blk -= 4096; }
    else if (blk <  8192) { in = Wo; out = pWo; Nd = DD; blk -= 6144; }
    else if (blk < 10240) { in = Cr; out = pCr; Nd = DD; blk -= 8192; }
    else if (blk < 18432) { in = Ck; out = pCk; Nd = FF; blk -= 10240; }
    else                  { in = Cv; out = pCv; Nd = DD; blk -= 18432; }
    const int i = blk * 256 + threadIdx.x;
    const int kh = i / Nd, n = i - kh * Nd;
    const float lo = in[(size_t)(2 * kh)     * Nd + n];
    const float hi = in[(size_t)(2 * kh + 1) * Nd + n];
    __half2 h = __floats2half2_rn(lo, hi);
    out[i] = *(unsigned*)&h;
}

// ---------------- fused LayerNorm + token-shift mix -> half-packed GEMM operands ----------------
template<int NOUT>
__global__ void __launch_bounds__(256) ln_mix_kernel(
    const float* __restrict__ x, const float* __restrict__ g, const float* __restrict__ b,
    const float* __restrict__ x0,
    const float* __restrict__ m0, const float* __restrict__ m1, const float* __restrict__ m2,
    unsigned* __restrict__ o0, unsigned* __restrict__ o1, unsigned* __restrict__ o2,
    float* __restrict__ last)
{
    const int row = blockIdx.x;
    const int t   = row & (TT - 1);
    const int bi  = row >> 10;
    const int tid = threadIdx.x;

    float4 xc = ((const float4*)(x + (size_t)row * DD))[tid];
    float4 xq = make_float4(0.f, 0.f, 0.f, 0.f);
    if (t > 0) xq = ((const float4*)(x + (size_t)(row - 1) * DD))[tid];

    float s0 = xc.x + xc.y + xc.z + xc.w;
    float q0 = xc.x*xc.x + xc.y*xc.y + xc.z*xc.z + xc.w*xc.w;
    float s1 = xq.x + xq.y + xq.z + xq.w;
    float q1 = xq.x*xq.x + xq.y*xq.y + xq.z*xq.z + xq.w*xq.w;
#pragma unroll
    for (int o = 16; o; o >>= 1) {
        s0 += __shfl_xor_sync(0xffffffffu, s0, o);
        q0 += __shfl_xor_sync(0xffffffffu, q0, o);
        s1 += __shfl_xor_sync(0xffffffffu, s1, o);
        q1 += __shfl_xor_sync(0xffffffffu, q1, o);
    }
    __shared__ float sh[32];
    const int w = tid >> 5, l = tid & 31;
    if (l == 0) { sh[w] = s0; sh[8 + w] = q0; sh[16 + w] = s1; sh[24 + w] = q1; }
    __syncthreads();
    s0 = 0.f; q0 = 0.f; s1 = 0.f; q1 = 0.f;
#pragma unroll
    for (int i = 0; i < 8; i++) {
        s0 += sh[i]; q0 += sh[8 + i]; s1 += sh[16 + i]; q1 += sh[24 + i];
    }
    const float mean0 = s0 * (1.0f / DD);
    const float rstd0 = rsqrtf(q0 * (1.0f / DD) - mean0 * mean0 + 1e-3f);
    const float mean1 = s1 * (1.0f / DD);
    const float rstd1 = rsqrtf(q1 * (1.0f / DD) - mean1 * mean1 + 1e-3f);

    float4 gg = ((const float4*)g)[tid];
    float4 bb = ((const float4*)b)[tid];

    float4 xnc;
    xnc.x = (xc.x - mean0) * rstd0 * gg.x + bb.x;
    xnc.y = (xc.y - mean0) * rstd0 * gg.y + bb.y;
    xnc.z = (xc.z - mean0) * rstd0 * gg.z + bb.z;
    xnc.w = (xc.w - mean0) * rstd0 * gg.w + bb.w;

    float4 xnp;
    if (t > 0) {
        xnp.x = (xq.x - mean1) * rstd1 * gg.x + bb.x;
        xnp.y = (xq.y - mean1) * rstd1 * gg.y + bb.y;
        xnp.z = (xq.z - mean1) * rstd1 * gg.z + bb.z;
        xnp.w = (xq.w - mean1) * rstd1 * gg.w + bb.w;
    } else {
        xnp = ((const float4*)(x0 + (size_t)bi * DD))[tid];
    }

    {
        float4 m = ((const float4*)m0)[tid];
        __half2 p0 = __floats2half2_rn(xnp.x + (xnc.x - xnp.x) * m.x, xnp.y + (xnc.y - xnp.y) * m.y);
        __half2 p1 = __floats2half2_rn(xnp.z + (xnc.z - xnp.z) * m.z, xnp.w + (xnc.w - xnp.w) * m.w);
        uint2 wv; wv.x = *(unsigned*)&p0; wv.y = *(unsigned*)&p1;
        ((uint2*)o0)[(size_t)row * D4 + tid] = wv;
    }
    if (NOUT >= 2) {
        float4 m = ((const float4*)m1)[tid];
        __half2 p0 = __floats2half2_rn(xnp.x + (xnc.x - xnp.x) * m.x, xnp.y + (xnc.y - xnp.y) * m.y);
        __half2 p1 = __floats2half2_rn(xnp.z + (xnc.z - xnp.z) * m.z, xnp.w + (xnc.w - xnp.w) * m.w);
        uint2 wv; wv.x = *(unsigned*)&p0; wv.y = *(unsigned*)&p1;
        ((uint2*)o1)[(size_t)row * D4 + tid] = wv;
    }
    if (NOUT >= 3) {
        float4 m = ((const float4*)m2)[tid];
        __half2 p0 = __floats2half2_rn(xnp.x + (xnc.x - xnp.x) * m.x, xnp.y + (xnc.y - xnp.y) * m.y);
        __half2 p1 = __floats2half2_rn(xnp.z + (xnc.z - xnp.z) * m.z, xnp.w + (xnc.w - xnp.w) * m.w);
        uint2 wv; wv.x = *(unsigned*)&p0; wv.y = *(unsigned*)&p1;
        ((uint2*)o2)[(size_t)row * D4 + tid] = wv;
    }
    if (t == TT - 1) {
        ((float4*)(last + (size_t)bi * DD))[tid] = xnc;
    }
}

// ---------------- WKV scan: half inputs, 8-deep prefetch, fast exp/div, 32-thr blocks ----------------
__global__ void __launch_bounds__(32) wkv_kernel(
    const __half* __restrict__ k, const __half* __restrict__ v, const __half* __restrict__ r,
    const float* __restrict__ a0, const float* __restrict__ b0, const float* __restrict__ p0,
    const float* __restrict__ decay, const float* __restrict__ first,
    __half* __restrict__ rw,
    float* __restrict__ aa_o, float* __restrict__ bb_o, float* __restrict__ pp_o)
{
    const int idx = blockIdx.x * blockDim.x + threadIdx.x;
    if (idx >= BB * DD) return;
    const int d = idx & (DD - 1), b = idx >> 10;
    float aa = a0[idx], bb = b0[idx], pp = p0[idx];
    const float w = -__expf(decay[d]);
    const float u = first[d];
    const size_t base = (size_t)b * TT * DD + d;

    float kb[8], vb[8], rb[8];
#pragma unroll
    for (int j = 0; j < 8; j++) {
        const size_t off = base + (size_t)j * DD;
        kb[j] = __half2float(k[off]);
        vb[j] = __half2float(v[off]);
        rb[j] = __half2float(r[off]);
    }

    for (int t0 = 0; t0 < TT; t0 += 8) {
        float kn[8], vn[8], rn[8];
        if (t0 + 8 < TT) {
#pragma unroll
            for (int j = 0; j < 8; j++) {
                const size_t off = base + (size_t)(t0 + 8 + j) * DD;
                kn[j] = __half2float(k[off]);
                vn[j] = __half2float(v[off]);
                rn[j] = __half2float(r[off]);
            }
        } else {
#pragma unroll
            for (int j = 0; j < 8; j++) { kn[j] = 0.f; vn[j] = 0.f; rn[j] = 0.f; }
        }
#pragma unroll
        for (int j = 0; j < 8; j++) {
            const float kt = kb[j], vt = vb[j], rt = rb[j];
            float ww = u + kt;
            float p  = fmaxf(pp, ww);
            float e1 = __expf(pp - p), e2 = __expf(ww - p);
            float wkv = __fdividef(e1 * aa + e2 * vt, e1 * bb + e2);
            rw[base + (size_t)(t0 + j) * DD] = __float2half_rn(rt * wkv);
            float ww2 = pp + w;
            float p2  = fmaxf(ww2, kt);
            float e1b = __expf(ww2 - p2), e2b = __expf(kt - p2);
            aa = e1b * aa + e2b * vt;
            bb = e1b * bb + e2b;
            pp = p2;
        }
#pragma unroll
        for (int j = 0; j < 8; j++) { kb[j] = kn[j]; vb[j] = vn[j]; rb[j] = rn[j]; }
    }
    aa_o[idx] = aa; bb_o[idx] = bb; pp_o[idx] = pp;
}

// ---------------- fp16 tensor-core GEMM: 128x128x16, mma.m16n8k16, cp.async 3-stage ----------------
// Inner loop byte-identical to the proven R11 core. CTA-uniform operand selection for fused modes.
// EPI: 1=sigmoid, 2=relu^2->half, 3=acc+X, 4=X+S*acc,
//      7=KVR fused -> HALF out (z selects {A,B,C}; sigmoid iff z==2),
//      8=CM pair  (bx<32: relu^2->half N=4096; bx>=32: sigmoid fp32 N=1024)

#define CP16(d, s)  asm volatile("cp.async.cg.shared.global [%0], [%1], 16;\n" :: "r"(d), "l"(s) : "memory")
#define CPCOMMIT()  asm volatile("cp.async.commit_group;\n" ::: "memory")
#define CPWAIT1()   asm volatile("cp.async.wait_group 1;\n" ::: "memory")
#define CPWAIT0()   asm volatile("cp.async.wait_group 0;\n" ::: "memory")

__device__ __forceinline__ void mma16816(float* c, const unsigned* a, const unsigned* b) {
    asm volatile(
        "mma.sync.aligned.m16n8k16.row.col.f32.f16.f16.f32 "
        "{%0,%1,%2,%3}, {%4,%5,%6,%7}, {%8,%9}, {%0,%1,%2,%3};\n"
        : "+f"(c[0]), "+f"(c[1]), "+f"(c[2]), "+f"(c[3])
        : "r"(a[0]), "r"(a[1]), "r"(a[2]), "r"(a[3]), "r"(b[0]), "r"(b[1]));
}

#define A_STRIDE 12
#define B_STRIDE 136
#define A_STAGE_W (128 * A_STRIDE)
#define B_STAGE_W (8 * B_STRIDE)

template<int EPI>
__global__ void __launch_bounds__(128, 2) tgemm(
    const unsigned* __restrict__ A32, const unsigned* __restrict__ B32, void* __restrict__ Cp,
    int M, int N, int K,
    const float* __restrict__ X, const float* __restrict__ S,
    const unsigned* A2, const unsigned* B2, void* C2,
    const unsigned* A3, const unsigned* B3, void* C3)
{
    __shared__ __align__(16) unsigned sA[3 * A_STAGE_W];
    __shared__ __align__(16) unsigned sB[3 * B_STAGE_W];

    const int tid  = threadIdx.x;
    const int lane = tid & 31;
    const int warp = tid >> 5;
    const int wm   = warp >> 1;
    const int wn   = warp & 1;
    const int bm   = blockIdx.y * 128;
    int bn = blockIdx.x * 128;

    // ---- CTA-uniform operand selection for fused modes ----
    const unsigned* Ause = A32;
    const unsigned* Buse = B32;
    void* Cuse = Cp;
    bool doSig = false;
    bool crMode = false;
    if (EPI == 7) {
        const int z = blockIdx.z;
        if (z == 1)      { Ause = A2; Buse = B2; Cuse = C2; }
        else if (z == 2) { Ause = A3; Buse = B3; Cuse = C3; doSig = true; }
    } else if (EPI == 8) {
        if (blockIdx.x >= 32) {
            Ause = A2; Buse = B2; Cuse = C2;
            N = DD;
            bn = (blockIdx.x - 32) * 128;
            crMode = true; doSig = true;
        }
    }
    const int Kw = K >> 1;

    const uint32_t aB = (uint32_t)__cvta_generic_to_shared(sA);
    const uint32_t bB = (uint32_t)__cvta_generic_to_shared(sB);

    const unsigned* aRow = Ause + (size_t)(bm + tid) * Kw;
    const uint32_t  aD   = aB + tid * (A_STRIDE * 4);
    const int bkh = tid >> 4;
    const int bc  = tid & 15;
    const unsigned* bRow = Buse + bn + (size_t)bkh * N;
    const uint32_t  bD   = bB + bkh * (B_STRIDE * 4);

    auto issue = [&](int s, int st) {
        const int k0w = s << 3;
        const unsigned* as = aRow + k0w;
        uint32_t ad = aD + st * (A_STAGE_W * 4);
        CP16(ad,      as);
        CP16(ad + 16, as + 4);
        const unsigned* bs = bRow + (size_t)k0w * N;
        uint32_t bd = bD + st * (B_STAGE_W * 4);
        CP16(bd + bc * 16,        bs + bc * 4);
        CP16(bd + (bc + 16) * 16, bs + (bc + 16) * 4);
        CPCOMMIT();
    };

    float acc[4][8][4];
#pragma unroll
    for (int i = 0; i < 4; i++)
#pragma unroll
        for (int j = 0; j < 8; j++)
#pragma unroll
            for (int e = 0; e < 4; e++) acc[i][j][e] = 0.f;

    const int aT = wm * 768 + (lane >> 2) * A_STRIDE + (lane & 3);
    const int bT = (lane & 3) * B_STRIDE + wn * 64 + (lane >> 2);

    const int ns = K >> 4;
    issue(0, 0); issue(1, 1);
    int st = 0, st2 = 2;
    for (int s = 0; s < ns; s++) {
        if (s == ns - 1) { CPWAIT0(); } else { CPWAIT1(); }
        __syncthreads();
        if (s + 2 < ns) { issue(s + 2, st2); st2 = (st2 == 2) ? 0 : st2 + 1; }

        const unsigned* Aw = sA + st * A_STAGE_W;
        const unsigned* Bw = sB + st * B_STAGE_W;
        unsigned af[4][4], bf[8][2];
#pragma unroll
        for (int mt = 0; mt < 4; mt++)
#pragma unroll
            for (int r = 0; r < 4; r++)
                af[mt][r] = Aw[aT + mt * 192 + (r & 1) * 96 + (r >> 1) * 4];
#pragma unroll
        for (int nt = 0; nt < 8; nt++)
#pragma unroll
            for (int r = 0; r < 2; r++)
                bf[nt][r] = Bw[bT + nt * 8 + r * (4 * B_STRIDE)];
#pragma unroll
        for (int mt = 0; mt < 4; mt++)
#pragma unroll
            for (int nt = 0; nt < 8; nt++)
                mma16816(acc[mt][nt], af[mt], bf[nt]);

        st = (st == 2) ? 0 : st + 1;
    }

    // ---- epilogue ----
    float* C = (float*)Cuse;
    const int rbase = bm + wm * 64 + (lane >> 2);
    const int cbase = bn + wn * 64 + ((lane & 3) << 1);
#pragma unroll
    for (int mt = 0; mt < 4; mt++) {
#pragma unroll
        for (int h = 0; h < 2; h++) {
            const int row = rbase + mt * 16 + h * 8;
#pragma unroll
            for (int nt = 0; nt < 8; nt++) {
                const int col = cbase + nt * 8;
                const size_t idx = (size_t)row * N + col;
                float v0 = acc[mt][nt][h * 2 + 0];
                float v1 = acc[mt][nt][h * 2 + 1];
                if (EPI == 1) {
                    v0 = 1.f / (1.f + expf(-v0));
                    v1 = 1.f / (1.f + expf(-v1));
                    float2 o; o.x = v0; o.y = v1;
                    *(float2*)&C[idx] = o;
                } else if (EPI == 2) {
                    v0 = fmaxf(v0, 0.f); v0 *= v0;
                    v1 = fmaxf(v1, 0.f); v1 *= v1;
                    __half2 hh = __floats2half2_rn(v0, v1);
                    *(unsigned*)((__half*)Cuse + idx) = *(unsigned*)&hh;
                } else if (EPI == 3) {
                    float2 xv = *(const float2*)&X[idx];
                    float2 o; o.x = v0 + xv.x; o.y = v1 + xv.y;
                    *(float2*)&C[idx] = o;
                } else if (EPI == 4) {
                    float2 xv = *(const float2*)&X[idx];
                    float2 sv = *(const float2*)&S[idx];
                    float2 o;
                    o.x = xv.x + sv.x * v0;
                    o.y = xv.y + sv.y * v1;
                    *(float2*)&C[idx] = o;
                } else if (EPI == 7) {
                    if (doSig) {
                        v0 = 1.f / (1.f + expf(-v0));
                        v1 = 1.f / (1.f + expf(-v1));
                    }
                    __half2 hh = __floats2half2_rn(v0, v1);
                    *(unsigned*)((__half*)Cuse + idx) = *(unsigned*)&hh;
                } else if (EPI == 8) {
                    if (crMode) {
                        v0 = 1.f / (1.f + expf(-v0));
                        v1 = 1.f / (1.f + expf(-v1));
                        float2 o; o.x = v0; o.y = v1;
                        *(float2*)&C[idx] = o;
                    } else {
                        v0 = fmaxf(v0, 0.f); v0 *= v0;
                        v1 = fmaxf(v1, 0.f); v1 *= v1;
                        __half2 hh = __floats2half2_rn(v0, v1);
                        *(unsigned*)((__half*)Cuse + idx) = *(unsigned*)&hh;
                    }
                } else {
                    float2 o; o.x = v0; o.y = v1;
                    *(float2*)&C[idx] = o;
                }
            }
        }
    }
}

// ---------------- host ----------------
extern "C" void kernel_launch(void* const* d_in, const int* in_sizes, int n_in,
                              void* d_out, int out_size)
{
    const float* x        = (const float*)d_in[0];
    const float* att_x    = (const float*)d_in[1];
    const float* att_a    = (const float*)d_in[2];
    const float* att_b    = (const float*)d_in[3];
    const float* att_p    = (const float*)d_in[4];
    const float* ffn_x    = (const float*)d_in[5];
    const float* ln1_g    = (const float*)d_in[6];
    const float* ln1_b    = (const float*)d_in[7];
    const float* ln2_g    = (const float*)d_in[8];
    const float* ln2_b    = (const float*)d_in[9];
    const float* tm_mix_k = (const float*)d_in[10];
    const float* tm_mix_v = (const float*)d_in[11];
    const float* tm_mix_r = (const float*)d_in[12];
    const float* tm_decay = (const float*)d_in[13];
    const float* tm_first = (const float*)d_in[14];
    const float* Wk       = (const float*)d_in[15];
    const float* Wv       = (const float*)d_in[16];
    const float* Wr       = (const float*)d_in[17];
    const float* Wo       = (const float*)d_in[18];
    const float* cm_mix_k = (const float*)d_in[19];
    const float* cm_mix_r = (const float*)d_in[20];
    const float* Ck       = (const float*)d_in[21];
    const float* Cr       = (const float*)d_in[22];
    const float* Cv       = (const float*)d_in[23];

    float* out = (float*)d_out;
    const size_t OFS_XN1 = (size_t)MM * DD;
    const size_t OFS_AA  = OFS_XN1 + (size_t)BB * DD;
    const size_t OFS_BB  = OFS_AA  + (size_t)BB * DD;
    const size_t OFS_PP  = OFS_BB  + (size_t)BB * DD;
    const size_t OFS_XN2 = OFS_PP  + (size_t)BB * DD;

    float *x1, *rc;
    unsigned *mk, *mv, *mr, *mck, *mcr;
    __half *kk, *vv, *rr, *rw, *kc;
    unsigned *pWk, *pWv, *pWr, *pWo, *pCr, *pCk, *pCv;
    cudaGetSymbolAddress((void**)&mk,  g_mk);
    cudaGetSymbolAddress((void**)&mv,  g_mv);
    cudaGetSymbolAddress((void**)&mr,  g_mr);
    cudaGetSymbolAddress((void**)&kk,  g_k);
    cudaGetSymbolAddress((void**)&vv,  g_v);
    cudaGetSymbolAddress((void**)&rr,  g_r);
    cudaGetSymbolAddress((void**)&rw,  g_rw);
    cudaGetSymbolAddress((void**)&x1,  g_x1);
    cudaGetSymbolAddress((void**)&mck, g_mck);
    cudaGetSymbolAddress((void**)&mcr, g_mcr);
    cudaGetSymbolAddress((void**)&kc,  g_kc);
    cudaGetSymbolAddress((void**)&rc,  g_rc);
    cudaGetSymbolAddress((void**)&pWk, g_pWk);
    cudaGetSymbolAddress((void**)&pWv, g_pWv);
    cudaGetSymbolAddress((void**)&pWr, g_pWr);
    cudaGetSymbolAddress((void**)&pWo, g_pWo);
    cudaGetSymbolAddress((void**)&pCr, g_pCr);
    cudaGetSymbolAddress((void**)&pCk, g_pCk);
    cudaGetSymbolAddress((void**)&pCv, g_pCv);

    // 0) pack all 7 weights in one launch
    pack_all<<<26624, 256>>>(Wk, Wv, Wr, Wo, Cr, Ck, Cv,
                             pWk, pWv, pWr, pWo, pCr, pCk, pCv);

    // 1+2) fused ln1 + time-mix -> mk/mv/mr (half-packed) + xn_last
    ln_mix_kernel<3><<<MM, 256>>>(x, ln1_g, ln1_b, att_x,
                                  tm_mix_k, tm_mix_v, tm_mix_r,
                                  mk, mv, mr, out + OFS_XN1);

    // 3) fused K|V|R GEMMs -> half (one launch, grid.z selects; sigmoid on z==2)
    dim3 gKVR(DD / 128, MM / 128, 3);
    tgemm<7><<<gKVR, 128>>>(mk, pWk, kk, MM, DD, DD, nullptr, nullptr,
                            mv, pWv, vv, mr, pWr, rr);

    // 4) WKV scan (half inputs, fused r*wkv -> half), state outputs
    wkv_kernel<<<(BB * DD) / 32, 32>>>(kk, vv, rr, att_a, att_b, att_p,
                                       tm_decay, tm_first, rw,
                                       out + OFS_AA, out + OFS_BB, out + OFS_PP);

    // 5) x1 = x + (r*wkv) @ Wo
    dim3 gD(DD / 128, MM / 128);
    tgemm<3><<<gD, 128>>>((const unsigned*)rw, pWo, x1, MM, DD, DD, x, nullptr,
                          nullptr, nullptr, nullptr, nullptr, nullptr, nullptr);

    // 6+7) fused ln2 + channel-mix -> mck/mcr (half-packed) + xn2_last
    ln_mix_kernel<2><<<MM, 256>>>(x1, ln2_g, ln2_b, ffn_x,
                                  cm_mix_k, cm_mix_r, nullptr,
                                  mck, mcr, nullptr, out + OFS_XN2);

    // 8+9) fused: kc = relu(mck @ Ck)^2 -> half  AND  rc = sigmoid(mcr @ Cr)
    dim3 gCM(40, MM / 128);
    tgemm<8><<<gCM, 128>>>(mck, pCk, kc, MM, FF, DD, nullptr, nullptr,
                           mcr, pCr, rc, nullptr, nullptr, nullptr);

    // 10) out = x1 + rc * (kc @ Cv)   [M=8192, N=1024, K=4096]
    tgemm<4><<<gD, 128>>>((const unsigned*)kc, pCv, out, MM, DD, FF, x1, rc,
                          nullptr, nullptr, nullptr, nullptr, nullptr, nullptr);
}

// round 17
// speedup vs baseline: 1.2291x; 1.0547x over previous
#include <cuda_runtime.h>
#include <cuda_fp16.h>
#include <cstdint>

#define BB 8
#define TT 1024
#define DD 1024
#define FF 4096
#define MM (BB*TT)          // 8192 rows
#define D4 (DD/4)
#define NCH (BB*DD)         // 8192 channels
#define NCHUNK 4
#define CLEN (TT/NCHUNK)    // 256

// ---------------- scratch (static device allocations; allowed) ----------------
__device__ unsigned g_mk [MM*DD/2];
__device__ unsigned g_mv [MM*DD/2];
__device__ unsigned g_mr [MM*DD/2];
__device__ __half   g_k  [MM*DD];     // KVR GEMM outputs (half)
__device__ __half   g_v  [MM*DD];
__device__ __half   g_r  [MM*DD];
__device__ __half   g_rw [MM*DD];
__device__ float    g_x1 [MM*DD];
__device__ unsigned g_mck[MM*DD/2];
__device__ unsigned g_mcr[MM*DD/2];
__device__ __half   g_kc [MM*FF];
__device__ float    g_rc [MM*DD];
// WKV chunked-scan buffers
__device__ float g_sumA[NCHUNK*NCH];
__device__ float g_sumB[NCHUNK*NCH];
__device__ float g_sumP[NCHUNK*NCH];
__device__ float g_preA[NCHUNK*NCH];
__device__ float g_preB[NCHUNK*NCH];
__device__ float g_preP[NCHUNK*NCH];
// k-pair-packed fp16 weights
__device__ unsigned g_pWk[(DD/2)*DD];
__device__ unsigned g_pWv[(DD/2)*DD];
__device__ unsigned g_pWr[(DD/2)*DD];
__device__ unsigned g_pWo[(DD/2)*DD];
__device__ unsigned g_pCr[(DD/2)*DD];
__device__ unsigned g_pCk[(DD/2)*FF];
__device__ unsigned g_pCv[(FF/2)*DD];

// ---------------- fused weight pack: all 7 matrices in ONE launch ----------------
__global__ void __launch_bounds__(256) pack_all(
    const float* __restrict__ Wk, const float* __restrict__ Wv, const float* __restrict__ Wr,
    const float* __restrict__ Wo, const float* __restrict__ Cr,
    const float* __restrict__ Ck, const float* __restrict__ Cv,
    unsigned* __restrict__ pWk, unsigned* __restrict__ pWv, unsigned* __restrict__ pWr,
    unsigned* __restrict__ pWo, unsigned* __restrict__ pCr,
    unsigned* __restrict__ pCk, unsigned* __restrict__ pCv)
{
    int blk = blockIdx.x;
    const float* in; unsigned* out; int Nd;
    if      (blk <  2048) { in = Wk; out = pWk; Nd = DD; }
    else if (blk <  4096) { in = Wv; out = pWv; Nd = DD; blk -= 2048; }
    else if (blk <  6144) { in = Wr; out = pWr; Nd = DD; blk -= 4096; }
    else if (blk <  8192) { in = Wo; out = pWo; Nd = DD; blk -= 6144; }
    else if (blk < 10240) { in = Cr; out = pCr; Nd = DD; blk -= 8192; }
    else if (blk < 18432) { in = Ck; out = pCk; Nd = FF; blk -= 10240; }
    else                  { in = Cv; out = pCv; Nd = DD; blk -= 18432; }
    const int i = blk * 256 + threadIdx.x;
    const int kh = i / Nd, n = i - kh * Nd;
    const float lo = in[(size_t)(2 * kh)     * Nd + n];
    const float hi = in[(size_t)(2 * kh + 1) * Nd + n];
    __half2 h = __floats2half2_rn(lo, hi);
    out[i] = *(unsigned*)&h;
}

// ---------------- fused LayerNorm + token-shift mix -> half-packed GEMM operands ----------------
template<int NOUT>
__global__ void __launch_bounds__(256) ln_mix_kernel(
    const float* __restrict__ x, const float* __restrict__ g, const float* __restrict__ b,
    const float* __restrict__ x0,
    const float* __restrict__ m0, const float* __restrict__ m1, const float* __restrict__ m2,
    unsigned* __restrict__ o0, unsigned* __restrict__ o1, unsigned* __restrict__ o2,
    float* __restrict__ last)
{
    const int row = blockIdx.x;
    const int t   = row & (TT - 1);
    const int bi  = row >> 10;
    const int tid = threadIdx.x;

    float4 xc = ((const float4*)(x + (size_t)row * DD))[tid];
    float4 xq = make_float4(0.f, 0.f, 0.f, 0.f);
    if (t > 0) xq = ((const float4*)(x + (size_t)(row - 1) * DD))[tid];

    float s0 = xc.x + xc.y + xc.z + xc.w;
    float q0 = xc.x*xc.x + xc.y*xc.y + xc.z*xc.z + xc.w*xc.w;
    float s1 = xq.x + xq.y + xq.z + xq.w;
    float q1 = xq.x*xq.x + xq.y*xq.y + xq.z*xq.z + xq.w*xq.w;
#pragma unroll
    for (int o = 16; o; o >>= 1) {
        s0 += __shfl_xor_sync(0xffffffffu, s0, o);
        q0 += __shfl_xor_sync(0xffffffffu, q0, o);
        s1 += __shfl_xor_sync(0xffffffffu, s1, o);
        q1 += __shfl_xor_sync(0xffffffffu, q1, o);
    }
    __shared__ float sh[32];
    const int w = tid >> 5, l = tid & 31;
    if (l == 0) { sh[w] = s0; sh[8 + w] = q0; sh[16 + w] = s1; sh[24 + w] = q1; }
    __syncthreads();
    s0 = 0.f; q0 = 0.f; s1 = 0.f; q1 = 0.f;
#pragma unroll
    for (int i = 0; i < 8; i++) {
        s0 += sh[i]; q0 += sh[8 + i]; s1 += sh[16 + i]; q1 += sh[24 + i];
    }
    const float mean0 = s0 * (1.0f / DD);
    const float rstd0 = rsqrtf(q0 * (1.0f / DD) - mean0 * mean0 + 1e-3f);
    const float mean1 = s1 * (1.0f / DD);
    const float rstd1 = rsqrtf(q1 * (1.0f / DD) - mean1 * mean1 + 1e-3f);

    float4 gg = ((const float4*)g)[tid];
    float4 bb = ((const float4*)b)[tid];

    float4 xnc;
    xnc.x = (xc.x - mean0) * rstd0 * gg.x + bb.x;
    xnc.y = (xc.y - mean0) * rstd0 * gg.y + bb.y;
    xnc.z = (xc.z - mean0) * rstd0 * gg.z + bb.z;
    xnc.w = (xc.w - mean0) * rstd0 * gg.w + bb.w;

    float4 xnp;
    if (t > 0) {
        xnp.x = (xq.x - mean1) * rstd1 * gg.x + bb.x;
        xnp.y = (xq.y - mean1) * rstd1 * gg.y + bb.y;
        xnp.z = (xq.z - mean1) * rstd1 * gg.z + bb.z;
        xnp.w = (xq.w - mean1) * rstd1 * gg.w + bb.w;
    } else {
        xnp = ((const float4*)(x0 + (size_t)bi * DD))[tid];
    }

    {
        float4 m = ((const float4*)m0)[tid];
        __half2 p0 = __floats2half2_rn(xnp.x + (xnc.x - xnp.x) * m.x, xnp.y + (xnc.y - xnp.y) * m.y);
        __half2 p1 = __floats2half2_rn(xnp.z + (xnc.z - xnp.z) * m.z, xnp.w + (xnc.w - xnp.w) * m.w);
        uint2 wv; wv.x = *(unsigned*)&p0; wv.y = *(unsigned*)&p1;
        ((uint2*)o0)[(size_t)row * D4 + tid] = wv;
    }
    if (NOUT >= 2) {
        float4 m = ((const float4*)m1)[tid];
        __half2 p0 = __floats2half2_rn(xnp.x + (xnc.x - xnp.x) * m.x, xnp.y + (xnc.y - xnp.y) * m.y);
        __half2 p1 = __floats2half2_rn(xnp.z + (xnc.z - xnp.z) * m.z, xnp.w + (xnc.w - xnp.w) * m.w);
        uint2 wv; wv.x = *(unsigned*)&p0; wv.y = *(unsigned*)&p1;
        ((uint2*)o1)[(size_t)row * D4 + tid] = wv;
    }
    if (NOUT >= 3) {
        float4 m = ((const float4*)m2)[tid];
        __half2 p0 = __floats2half2_rn(xnp.x + (xnc.x - xnp.x) * m.x, xnp.y + (xnc.y - xnp.y) * m.y);
        __half2 p1 = __floats2half2_rn(xnp.z + (xnc.z - xnp.z) * m.z, xnp.w + (xnc.w - xnp.w) * m.w);
        uint2 wv; wv.x = *(unsigned*)&p0; wv.y = *(unsigned*)&p1;
        ((uint2*)o2)[(size_t)row * D4 + tid] = wv;
    }
    if (t == TT - 1) {
        ((float4*)(last + (size_t)bi * DD))[tid] = xnc;
    }
}

// ---------------- WKV phase 1: per-chunk local scan from identity -> summaries ----------------
// idx = c*NCH + ch; ch = b*DD + d. 32768 threads.
__global__ void __launch_bounds__(128) wkv_phase1(
    const __half* __restrict__ k, const __half* __restrict__ v,
    const float* __restrict__ decay,
    float* __restrict__ sumA, float* __restrict__ sumB, float* __restrict__ sumP)
{
    const int idx = blockIdx.x * blockDim.x + threadIdx.x;
    if (idx >= NCHUNK * NCH) return;
    const int ch = idx & (NCH - 1);
    const int c  = idx >> 13;
    const int d  = ch & (DD - 1), b = ch >> 10;
    const float w = -__expf(decay[d]);
    const size_t base = (size_t)b * TT * DD + (size_t)(c * CLEN) * DD + d;

    float aa = 0.f, bb = 0.f, pp = -1e30f;

    float kb[8], vb[8];
#pragma unroll
    for (int j = 0; j < 8; j++) {
        const size_t off = base + (size_t)j * DD;
        kb[j] = __half2float(k[off]);
        vb[j] = __half2float(v[off]);
    }
    for (int t0 = 0; t0 < CLEN; t0 += 8) {
        float kn[8], vn[8];
        if (t0 + 8 < CLEN) {
#pragma unroll
            for (int j = 0; j < 8; j++) {
                const size_t off = base + (size_t)(t0 + 8 + j) * DD;
                kn[j] = __half2float(k[off]);
                vn[j] = __half2float(v[off]);
            }
        } else {
#pragma unroll
            for (int j = 0; j < 8; j++) { kn[j] = 0.f; vn[j] = 0.f; }
        }
#pragma unroll
        for (int j = 0; j < 8; j++) {
            const float kt = kb[j], vt = vb[j];
            float ww2 = pp + w;
            float p2  = fmaxf(ww2, kt);
            float e1b = __expf(ww2 - p2), e2b = __expf(kt - p2);
            aa = e1b * aa + e2b * vt;
            bb = e1b * bb + e2b;
            pp = p2;
        }
#pragma unroll
        for (int j = 0; j < 8; j++) { kb[j] = kn[j]; vb[j] = vn[j]; }
    }
    sumA[idx] = aa; sumB[idx] = bb; sumP[idx] = pp;
}

// ---------------- WKV phase 2: combine summaries -> chunk prefixes + final states ----------------
__global__ void __launch_bounds__(128) wkv_phase2(
    const float* __restrict__ sumA, const float* __restrict__ sumB, const float* __restrict__ sumP,
    const float* __restrict__ a0, const float* __restrict__ b0, const float* __restrict__ p0,
    const float* __restrict__ decay,
    float* __restrict__ preA, float* __restrict__ preB, float* __restrict__ preP,
    float* __restrict__ aa_o, float* __restrict__ bb_o, float* __restrict__ pp_o)
{
    const int ch = blockIdx.x * blockDim.x + threadIdx.x;
    if (ch >= NCH) return;
    const int d = ch & (DD - 1);
    const float w  = -__expf(decay[d]);
    const float Lw = (float)CLEN * w;
    float a = a0[ch], b = b0[ch], p = p0[ch];
#pragma unroll
    for (int c = 0; c < NCHUNK; c++) {
        const int i = c * NCH + ch;
        preA[i] = a; preB[i] = b; preP[i] = p;
        const float pd = p + Lw;
        const float pc = sumP[i];
        const float pn = fmaxf(pd, pc);
        const float e0 = __expf(pd - pn), e1 = __expf(pc - pn);
        a = e0 * a + e1 * sumA[i];
        b = e0 * b + e1 * sumB[i];
        p = pn;
    }
    aa_o[ch] = a; bb_o[ch] = b; pp_o[ch] = p;
}

// ---------------- WKV phase 3: replay chunks from prefixes, emit r*wkv ----------------
__global__ void __launch_bounds__(128) wkv_phase3(
    const __half* __restrict__ k, const __half* __restrict__ v, const __half* __restrict__ r,
    const float* __restrict__ preA, const float* __restrict__ preB, const float* __restrict__ preP,
    const float* __restrict__ decay, const float* __restrict__ first,
    __half* __restrict__ rw)
{
    const int idx = blockIdx.x * blockDim.x + threadIdx.x;
    if (idx >= NCHUNK * NCH) return;
    const int ch = idx & (NCH - 1);
    const int c  = idx >> 13;
    const int d  = ch & (DD - 1), b = ch >> 10;
    const float w = -__expf(decay[d]);
    const float u = first[d];
    const size_t base = (size_t)b * TT * DD + (size_t)(c * CLEN) * DD + d;

    float aa = preA[idx], bb = preB[idx], pp = preP[idx];

    float kb[8], vb[8], rb[8];
#pragma unroll
    for (int j = 0; j < 8; j++) {
        const size_t off = base + (size_t)j * DD;
        kb[j] = __half2float(k[off]);
        vb[j] = __half2float(v[off]);
        rb[j] = __half2float(r[off]);
    }
    for (int t0 = 0; t0 < CLEN; t0 += 8) {
        float kn[8], vn[8], rn[8];
        if (t0 + 8 < CLEN) {
#pragma unroll
            for (int j = 0; j < 8; j++) {
                const size_t off = base + (size_t)(t0 + 8 + j) * DD;
                kn[j] = __half2float(k[off]);
                vn[j] = __half2float(v[off]);
                rn[j] = __half2float(r[off]);
            }
        } else {
#pragma unroll
            for (int j = 0; j < 8; j++) { kn[j] = 0.f; vn[j] = 0.f; rn[j] = 0.f; }
        }
#pragma unroll
        for (int j = 0; j < 8; j++) {
            const float kt = kb[j], vt = vb[j], rt = rb[j];
            float ww = u + kt;
            float p  = fmaxf(pp, ww);
            float e1 = __expf(pp - p), e2 = __expf(ww - p);
            float wkv = __fdividef(e1 * aa + e2 * vt, e1 * bb + e2);
            rw[base + (size_t)(t0 + j) * DD] = __float2half_rn(rt * wkv);
            float ww2 = pp + w;
            float p2  = fmaxf(ww2, kt);
            float e1b = __expf(ww2 - p2), e2b = __expf(kt - p2);
            aa = e1b * aa + e2b * vt;
            bb = e1b * bb + e2b;
            pp = p2;
        }
#pragma unroll
        for (int j = 0; j < 8; j++) { kb[j] = kn[j]; vb[j] = vn[j]; rb[j] = rn[j]; }
    }
}

// ---------------- fp16 tensor-core GEMM: 128x128x16, mma.m16n8k16, cp.async 3-stage ----------------
// EPI: 1=sigmoid, 2=relu^2->half, 3=acc+X, 4=X+S*acc,
//      7=KVR fused -> HALF out (z selects {A,B,C}; sigmoid iff z==2),
//      8=CM pair  (bx<32: relu^2->half N=4096; bx>=32: sigmoid fp32 N=1024)

#define CP16(d, s)  asm volatile("cp.async.cg.shared.global [%0], [%1], 16;\n" :: "r"(d), "l"(s) : "memory")
#define CPCOMMIT()  asm volatile("cp.async.commit_group;\n" ::: "memory")
#define CPWAIT1()   asm volatile("cp.async.wait_group 1;\n" ::: "memory")
#define CPWAIT0()   asm volatile("cp.async.wait_group 0;\n" ::: "memory")

__device__ __forceinline__ void mma16816(float* c, const unsigned* a, const unsigned* b) {
    asm volatile(
        "mma.sync.aligned.m16n8k16.row.col.f32.f16.f16.f32 "
        "{%0,%1,%2,%3}, {%4,%5,%6,%7}, {%8,%9}, {%0,%1,%2,%3};\n"
        : "+f"(c[0]), "+f"(c[1]), "+f"(c[2]), "+f"(c[3])
        : "r"(a[0]), "r"(a[1]), "r"(a[2]), "r"(a[3]), "r"(b[0]), "r"(b[1]));
}

#define A_STRIDE 12
#define B_STRIDE 136
#define A_STAGE_W (128 * A_STRIDE)
#define B_STAGE_W (8 * B_STRIDE)

template<int EPI>
__global__ void __launch_bounds__(128, 2) tgemm(
    const unsigned* __restrict__ A32, const unsigned* __restrict__ B32, void* __restrict__ Cp,
    int M, int N, int K,
    const float* __restrict__ X, const float* __restrict__ S,
    const unsigned* A2, const unsigned* B2, void* C2,
    const unsigned* A3, const unsigned* B3, void* C3)
{
    __shared__ __align__(16) unsigned sA[3 * A_STAGE_W];
    __shared__ __align__(16) unsigned sB[3 * B_STAGE_W];

    const int tid  = threadIdx.x;
    const int lane = tid & 31;
    const int warp = tid >> 5;
    const int wm   = warp >> 1;
    const int wn   = warp & 1;
    const int bm   = blockIdx.y * 128;
    int bn = blockIdx.x * 128;

    const unsigned* Ause = A32;
    const unsigned* Buse = B32;
    void* Cuse = Cp;
    bool doSig = false;
    bool crMode = false;
    if (EPI == 7) {
        const int z = blockIdx.z;
        if (z == 1)      { Ause = A2; Buse = B2; Cuse = C2; }
        else if (z == 2) { Ause = A3; Buse = B3; Cuse = C3; doSig = true; }
    } else if (EPI == 8) {
        if (blockIdx.x >= 32) {
            Ause = A2; Buse = B2; Cuse = C2;
            N = DD;
            bn = (blockIdx.x - 32) * 128;
            crMode = true; doSig = true;
        }
    }
    const int Kw = K >> 1;

    const uint32_t aB = (uint32_t)__cvta_generic_to_shared(sA);
    const uint32_t bB = (uint32_t)__cvta_generic_to_shared(sB);

    const unsigned* aRow = Ause + (size_t)(bm + tid) * Kw;
    const uint32_t  aD   = aB + tid * (A_STRIDE * 4);
    const int bkh = tid >> 4;
    const int bc  = tid & 15;
    const unsigned* bRow = Buse + bn + (size_t)bkh * N;
    const uint32_t  bD   = bB + bkh * (B_STRIDE * 4);

    auto issue = [&](int s, int st) {
        const int k0w = s << 3;
        const unsigned* as = aRow + k0w;
        uint32_t ad = aD + st * (A_STAGE_W * 4);
        CP16(ad,      as);
        CP16(ad + 16, as + 4);
        const unsigned* bs = bRow + (size_t)k0w * N;
        uint32_t bd = bD + st * (B_STAGE_W * 4);
        CP16(bd + bc * 16,        bs + bc * 4);
        CP16(bd + (bc + 16) * 16, bs + (bc + 16) * 4);
        CPCOMMIT();
    };

    float acc[4][8][4];
#pragma unroll
    for (int i = 0; i < 4; i++)
#pragma unroll
        for (int j = 0; j < 8; j++)
#pragma unroll
            for (int e = 0; e < 4; e++) acc[i][j][e] = 0.f;

    const int aT = wm * 768 + (lane >> 2) * A_STRIDE + (lane & 3);
    const int bT = (lane & 3) * B_STRIDE + wn * 64 + (lane >> 2);

    const int ns = K >> 4;
    issue(0, 0); issue(1, 1);
    int st = 0, st2 = 2;
    for (int s = 0; s < ns; s++) {
        if (s == ns - 1) { CPWAIT0(); } else { CPWAIT1(); }
        __syncthreads();
        if (s + 2 < ns) { issue(s + 2, st2); st2 = (st2 == 2) ? 0 : st2 + 1; }

        const unsigned* Aw = sA + st * A_STAGE_W;
        const unsigned* Bw = sB + st * B_STAGE_W;
        unsigned af[4][4], bf[8][2];
#pragma unroll
        for (int mt = 0; mt < 4; mt++)
#pragma unroll
            for (int r = 0; r < 4; r++)
                af[mt][r] = Aw[aT + mt * 192 + (r & 1) * 96 + (r >> 1) * 4];
#pragma unroll
        for (int nt = 0; nt < 8; nt++)
#pragma unroll
            for (int r = 0; r < 2; r++)
                bf[nt][r] = Bw[bT + nt * 8 + r * (4 * B_STRIDE)];
#pragma unroll
        for (int mt = 0; mt < 4; mt++)
#pragma unroll
            for (int nt = 0; nt < 8; nt++)
                mma16816(acc[mt][nt], af[mt], bf[nt]);

        st = (st == 2) ? 0 : st + 1;
    }

    // ---- epilogue ----
    float* C = (float*)Cuse;
    const int rbase = bm + wm * 64 + (lane >> 2);
    const int cbase = bn + wn * 64 + ((lane & 3) << 1);
#pragma unroll
    for (int mt = 0; mt < 4; mt++) {
#pragma unroll
        for (int h = 0; h < 2; h++) {
            const int row = rbase + mt * 16 + h * 8;
#pragma unroll
            for (int nt = 0; nt < 8; nt++) {
                const int col = cbase + nt * 8;
                const size_t idx = (size_t)row * N + col;
                float v0 = acc[mt][nt][h * 2 + 0];
                float v1 = acc[mt][nt][h * 2 + 1];
                if (EPI == 1) {
                    v0 = 1.f / (1.f + expf(-v0));
                    v1 = 1.f / (1.f + expf(-v1));
                    float2 o; o.x = v0; o.y = v1;
                    *(float2*)&C[idx] = o;
                } else if (EPI == 2) {
                    v0 = fmaxf(v0, 0.f); v0 *= v0;
                    v1 = fmaxf(v1, 0.f); v1 *= v1;
                    __half2 hh = __floats2half2_rn(v0, v1);
                    *(unsigned*)((__half*)Cuse + idx) = *(unsigned*)&hh;
                } else if (EPI == 3) {
                    float2 xv = *(const float2*)&X[idx];
                    float2 o; o.x = v0 + xv.x; o.y = v1 + xv.y;
                    *(float2*)&C[idx] = o;
                } else if (EPI == 4) {
                    float2 xv = *(const float2*)&X[idx];
                    float2 sv = *(const float2*)&S[idx];
                    float2 o;
                    o.x = xv.x + sv.x * v0;
                    o.y = xv.y + sv.y * v1;
                    *(float2*)&C[idx] = o;
                } else if (EPI == 7) {
                    if (doSig) {
                        v0 = 1.f / (1.f + expf(-v0));
                        v1 = 1.f / (1.f + expf(-v1));
                    }
                    __half2 hh = __floats2half2_rn(v0, v1);
                    *(unsigned*)((__half*)Cuse + idx) = *(unsigned*)&hh;
                } else if (EPI == 8) {
                    if (crMode) {
                        v0 = 1.f / (1.f + expf(-v0));
                        v1 = 1.f / (1.f + expf(-v1));
                        float2 o; o.x = v0; o.y = v1;
                        *(float2*)&C[idx] = o;
                    } else {
                        v0 = fmaxf(v0, 0.f); v0 *= v0;
                        v1 = fmaxf(v1, 0.f); v1 *= v1;
                        __half2 hh = __floats2half2_rn(v0, v1);
                        *(unsigned*)((__half*)Cuse + idx) = *(unsigned*)&hh;
                    }
                } else {
                    float2 o; o.x = v0; o.y = v1;
                    *(float2*)&C[idx] = o;
                }
            }
        }
    }
}

// ---------------- host ----------------
extern "C" void kernel_launch(void* const* d_in, const int* in_sizes, int n_in,
                              void* d_out, int out_size)
{
    const float* x        = (const float*)d_in[0];
    const float* att_x    = (const float*)d_in[1];
    const float* att_a    = (const float*)d_in[2];
    const float* att_b    = (const float*)d_in[3];
    const float* att_p    = (const float*)d_in[4];
    const float* ffn_x    = (const float*)d_in[5];
    const float* ln1_g    = (const float*)d_in[6];
    const float* ln1_b    = (const float*)d_in[7];
    const float* ln2_g    = (const float*)d_in[8];
    const float* ln2_b    = (const float*)d_in[9];
    const float* tm_mix_k = (const float*)d_in[10];
    const float* tm_mix_v = (const float*)d_in[11];
    const float* tm_mix_r = (const float*)d_in[12];
    const float* tm_decay = (const float*)d_in[13];
    const float* tm_first = (const float*)d_in[14];
    const float* Wk       = (const float*)d_in[15];
    const float* Wv       = (const float*)d_in[16];
    const float* Wr       = (const float*)d_in[17];
    const float* Wo       = (const float*)d_in[18];
    const float* cm_mix_k = (const float*)d_in[19];
    const float* cm_mix_r = (const float*)d_in[20];
    const float* Ck       = (const float*)d_in[21];
    const float* Cr       = (const float*)d_in[22];
    const float* Cv       = (const float*)d_in[23];

    float* out = (float*)d_out;
    const size_t OFS_XN1 = (size_t)MM * DD;
    const size_t OFS_AA  = OFS_XN1 + (size_t)BB * DD;
    const size_t OFS_BB  = OFS_AA  + (size_t)BB * DD;
    const size_t OFS_PP  = OFS_BB  + (size_t)BB * DD;
    const size_t OFS_XN2 = OFS_PP  + (size_t)BB * DD;

    float *x1, *rc;
    unsigned *mk, *mv, *mr, *mck, *mcr;
    __half *kk, *vv, *rr, *rw, *kc;
    float *sumA, *sumB, *sumP, *preA, *preB, *preP;
    unsigned *pWk, *pWv, *pWr, *pWo, *pCr, *pCk, *pCv;
    cudaGetSymbolAddress((void**)&mk,  g_mk);
    cudaGetSymbolAddress((void**)&mv,  g_mv);
    cudaGetSymbolAddress((void**)&mr,  g_mr);
    cudaGetSymbolAddress((void**)&kk,  g_k);
    cudaGetSymbolAddress((void**)&vv,  g_v);
    cudaGetSymbolAddress((void**)&rr,  g_r);
    cudaGetSymbolAddress((void**)&rw,  g_rw);
    cudaGetSymbolAddress((void**)&x1,  g_x1);
    cudaGetSymbolAddress((void**)&mck, g_mck);
    cudaGetSymbolAddress((void**)&mcr, g_mcr);
    cudaGetSymbolAddress((void**)&kc,  g_kc);
    cudaGetSymbolAddress((void**)&rc,  g_rc);
    cudaGetSymbolAddress((void**)&sumA, g_sumA);
    cudaGetSymbolAddress((void**)&sumB, g_sumB);
    cudaGetSymbolAddress((void**)&sumP, g_sumP);
    cudaGetSymbolAddress((void**)&preA, g_preA);
    cudaGetSymbolAddress((void**)&preB, g_preB);
    cudaGetSymbolAddress((void**)&preP, g_preP);
    cudaGetSymbolAddress((void**)&pWk, g_pWk);
    cudaGetSymbolAddress((void**)&pWv, g_pWv);
    cudaGetSymbolAddress((void**)&pWr, g_pWr);
    cudaGetSymbolAddress((void**)&pWo, g_pWo);
    cudaGetSymbolAddress((void**)&pCr, g_pCr);
    cudaGetSymbolAddress((void**)&pCk, g_pCk);
    cudaGetSymbolAddress((void**)&pCv, g_pCv);

    // 0) pack all 7 weights in one launch
    pack_all<<<26624, 256>>>(Wk, Wv, Wr, Wo, Cr, Ck, Cv,
                             pWk, pWv, pWr, pWo, pCr, pCk, pCv);

    // 1+2) fused ln1 + time-mix -> mk/mv/mr (half-packed) + xn_last
    ln_mix_kernel<3><<<MM, 256>>>(x, ln1_g, ln1_b, att_x,
                                  tm_mix_k, tm_mix_v, tm_mix_r,
                                  mk, mv, mr, out + OFS_XN1);

    // 3) fused K|V|R GEMMs -> half (grid.z selects; sigmoid on z==2)
    dim3 gKVR(DD / 128, MM / 128, 3);
    tgemm<7><<<gKVR, 128>>>(mk, pWk, kk, MM, DD, DD, nullptr, nullptr,
                            mv, pWv, vv, mr, pWr, rr);

    // 4) WKV chunked scan: phase1 (local summaries) -> phase2 (prefixes + states) -> phase3 (outputs)
    wkv_phase1<<<(NCHUNK * NCH) / 128, 128>>>(kk, vv, tm_decay, sumA, sumB, sumP);
    wkv_phase2<<<NCH / 128, 128>>>(sumA, sumB, sumP, att_a, att_b, att_p, tm_decay,
                                   preA, preB, preP,
                                   out + OFS_AA, out + OFS_BB, out + OFS_PP);
    wkv_phase3<<<(NCHUNK * NCH) / 128, 128>>>(kk, vv, rr, preA, preB, preP,
                                              tm_decay, tm_first, rw);

    // 5) x1 = x + (r*wkv) @ Wo
    dim3 gD(DD / 128, MM / 128);
    tgemm<3><<<gD, 128>>>((const unsigned*)rw, pWo, x1, MM, DD, DD, x, nullptr,
                          nullptr, nullptr, nullptr, nullptr, nullptr, nullptr);

    // 6+7) fused ln2 + channel-mix -> mck/mcr (half-packed) + xn2_last
    ln_mix_kernel<2><<<MM, 256>>>(x1, ln2_g, ln2_b, ffn_x,
                                  cm_mix_k, cm_mix_r, nullptr,
                                  mck, mcr, nullptr, out + OFS_XN2);

    // 8+9) fused: kc = relu(mck @ Ck)^2 -> half  AND  rc = sigmoid(mcr @ Cr)
    dim3 gCM(40, MM / 128);
    tgemm<8><<<gCM, 128>>>(mck, pCk, kc, MM, FF, DD, nullptr, nullptr,
                           mcr, pCr, rc, nullptr, nullptr, nullptr);

    // 10) out = x1 + rc * (kc @ Cv)   [M=8192, N=1024, K=4096]
    tgemm<4><<<gD, 128>>>((const unsigned*)kc, pCv, out, MM, DD, FF, x1, rc,
                          nullptr, nullptr, nullptr, nullptr, nullptr, nullptr);
}